// round 4
// baseline (speedup 1.0000x reference)
#include <cuda_runtime.h>
#include <cstddef>

#define HIDDEN 1024
#define SEQ    2048
#define BATCH  2
#define NHEADS 16
#define HDIM   64
#define MROWS  (BATCH * SEQ)   // 4096

typedef unsigned long long u64;

// ---------------- scratch (no cudaMalloc allowed) ----------------
__device__ float g_q[BATCH * SEQ * HIDDEN];
__device__ float g_k[BATCH * SEQ * HIDDEN];
__device__ float g_v[BATCH * SEQ * HIDDEN];
__device__ float g_ctx[BATCH * SEQ * HIDDEN];

// ---------------- packed f32x2 helpers ----------------
__device__ __forceinline__ u64 pack_dup(float x) {
    u64 r; asm("mov.b64 %0, {%1, %1};" : "=l"(r) : "f"(x)); return r;
}
__device__ __forceinline__ u64 pack2(float x, float y) {
    u64 r; asm("mov.b64 %0, {%1, %2};" : "=l"(r) : "f"(x), "f"(y)); return r;
}
__device__ __forceinline__ u64 fma2(u64 a, u64 b, u64 c) {
    u64 d; asm("fma.rn.f32x2 %0, %1, %2, %3;" : "=l"(d) : "l"(a), "l"(b), "l"(c)); return d;
}
__device__ __forceinline__ float2 unpack2(u64 v) {
    float lo, hi; asm("mov.b64 {%0, %1}, %2;" : "=f"(lo), "=f"(hi) : "l"(v));
    return make_float2(lo, hi);
}

// ============================================================================
// GEMM: C[M,N] = A[M,K] @ W[N,K]^T + bias[N]   (torch Linear convention)
// 128x128 tile, BK=8, 256 threads, 8x8 per thread, f32x2 packed accumulation.
//
// MODE resolves scratch pointers ON DEVICE (the R3 bug was writing to the
// nullptr C param):
//   MODE 0: A = param, C = g_q
//   MODE 1: A = param, C = g_k
//   MODE 2: A = param, C = g_v
//   MODE 3: A = g_ctx, C = param
// ============================================================================
template <int MODE>
__global__ __launch_bounds__(256, 2)
void gemm_bias_kernel(const float* __restrict__ Ain, const float* __restrict__ W,
                      const float* __restrict__ bias, float* __restrict__ Cin)
{
    const int K = HIDDEN, N = HIDDEN;

    const float* __restrict__ A = (MODE == 3) ? (const float*)g_ctx : Ain;
    float* __restrict__ C =
        (MODE == 0) ? g_q :
        (MODE == 1) ? g_k :
        (MODE == 2) ? g_v : Cin;

    __shared__ float As[8][128];
    __shared__ float Bs[8][128];

    const int bm = blockIdx.y * 128;
    const int bn = blockIdx.x * 128;
    const int tid = threadIdx.x;
    const int tx = tid & 15;          // 0..15  (N direction, 8 cols each)
    const int ty = tid >> 4;          // 0..15  (M direction, 8 rows each)
    const int lrow = tid >> 1;        // 0..127
    const int lcol = (tid & 1) << 2;  // 0 or 4

    const float* Ap = A + (size_t)(bm + lrow) * K + lcol;
    const float* Wp = W + (size_t)(bn + lrow) * K + lcol;

    u64 acc[8][4];
#pragma unroll
    for (int i = 0; i < 8; i++)
#pragma unroll
        for (int j = 0; j < 4; j++) acc[i][j] = 0ull;

    for (int k0 = 0; k0 < K; k0 += 8) {
        float4 a4 = *(const float4*)(Ap + k0);
        float4 w4 = *(const float4*)(Wp + k0);
        As[lcol + 0][lrow] = a4.x; As[lcol + 1][lrow] = a4.y;
        As[lcol + 2][lrow] = a4.z; As[lcol + 3][lrow] = a4.w;
        Bs[lcol + 0][lrow] = w4.x; Bs[lcol + 1][lrow] = w4.y;
        Bs[lcol + 2][lrow] = w4.z; Bs[lcol + 3][lrow] = w4.w;
        __syncthreads();

#pragma unroll
        for (int k = 0; k < 8; k++) {
            float4 af0 = *(const float4*)&As[k][ty * 8];
            float4 af1 = *(const float4*)&As[k][ty * 8 + 4];
            ulonglong2 b0 = *(const ulonglong2*)&Bs[k][tx * 8];
            ulonglong2 b1 = *(const ulonglong2*)&Bs[k][tx * 8 + 4];
            u64 bp[4] = { b0.x, b0.y, b1.x, b1.y };
            u64 ad[8] = { pack_dup(af0.x), pack_dup(af0.y), pack_dup(af0.z), pack_dup(af0.w),
                          pack_dup(af1.x), pack_dup(af1.y), pack_dup(af1.z), pack_dup(af1.w) };
#pragma unroll
            for (int i = 0; i < 8; i++)
#pragma unroll
                for (int j = 0; j < 4; j++)
                    acc[i][j] = fma2(ad[i], bp[j], acc[i][j]);
        }
        __syncthreads();
    }

    float4 bias0 = *(const float4*)&bias[bn + tx * 8];
    float4 bias1 = *(const float4*)&bias[bn + tx * 8 + 4];
#pragma unroll
    for (int i = 0; i < 8; i++) {
        size_t row = (size_t)(bm + ty * 8 + i);
        float2 p0 = unpack2(acc[i][0]);
        float2 p1 = unpack2(acc[i][1]);
        float2 p2 = unpack2(acc[i][2]);
        float2 p3 = unpack2(acc[i][3]);
        float4 o0 = make_float4(p0.x + bias0.x, p0.y + bias0.y, p1.x + bias0.z, p1.y + bias0.w);
        float4 o1 = make_float4(p2.x + bias1.x, p2.y + bias1.y, p3.x + bias1.z, p3.y + bias1.w);
        *(float4*)&C[row * N + bn + tx * 8]     = o0;
        *(float4*)&C[row * N + bn + tx * 8 + 4] = o1;
    }
}

// ============================================================================
// Flash attention, fp32, one q-row per thread, 128 rows per CTA.
// grid = (SEQ/128, NHEADS, BATCH), block = 128
// Reads g_q/g_k/g_v, writes g_ctx (device globals only).
// ============================================================================
__global__ __launch_bounds__(128)
void attn_kernel()
{
    __shared__ float ks[64][64];
    __shared__ float vs[64][64];

    const int b = blockIdx.z;
    const int h = blockIdx.y;
    const int qrow = blockIdx.x * 128 + threadIdx.x;
    const float scale = 0.125f;  // 1/sqrt(64)

    const float* qp = g_q + ((size_t)b * SEQ + qrow) * HIDDEN + h * HDIM;
    u64 q2[32];
#pragma unroll
    for (int i = 0; i < 16; i++) {
        float4 v4 = *(const float4*)(qp + 4 * i);
        q2[2 * i]     = pack2(v4.x * scale, v4.y * scale);
        q2[2 * i + 1] = pack2(v4.z * scale, v4.w * scale);
    }

    u64 o2[32];
#pragma unroll
    for (int i = 0; i < 32; i++) o2[i] = 0ull;
    float mmax = -1e30f, lsum = 0.0f;

    const float* kbase = g_k + ((size_t)b * SEQ) * HIDDEN + h * HDIM;
    const float* vbase = g_v + ((size_t)b * SEQ) * HIDDEN + h * HDIM;

    for (int kt = 0; kt < SEQ; kt += 64) {
#pragma unroll
        for (int f = 0; f < 8; f++) {
            int idx = f * 128 + threadIdx.x;
            int r = idx >> 4;
            int c = (idx & 15) << 2;
            *(float4*)&ks[r][c] = *(const float4*)(kbase + (size_t)(kt + r) * HIDDEN + c);
            *(float4*)&vs[r][c] = *(const float4*)(vbase + (size_t)(kt + r) * HIDDEN + c);
        }
        __syncthreads();

#pragma unroll 1
        for (int j = 0; j < 64; j++) {
            const ulonglong2* krow = (const ulonglong2*)&ks[j][0];
            u64 sa = 0ull, sb = 0ull;
#pragma unroll
            for (int t = 0; t < 16; t++) {
                ulonglong2 kk = krow[t];
                sa = fma2(q2[2 * t],     kk.x, sa);
                sb = fma2(q2[2 * t + 1], kk.y, sb);
            }
            float2 fa = unpack2(sa);
            float2 fb = unpack2(sb);
            float s = (fa.x + fa.y) + (fb.x + fb.y);

            const ulonglong2* vrow = (const ulonglong2*)&vs[j][0];
            if (s <= mmax) {
                float p = __expf(s - mmax);
                lsum += p;
                u64 pd = pack_dup(p);
#pragma unroll
                for (int t = 0; t < 16; t++) {
                    ulonglong2 vv = vrow[t];
                    o2[2 * t]     = fma2(pd, vv.x, o2[2 * t]);
                    o2[2 * t + 1] = fma2(pd, vv.y, o2[2 * t + 1]);
                }
            } else {
                float r = __expf(mmax - s);
                mmax = s;
                lsum = lsum * r + 1.0f;
                u64 rd = pack_dup(r);
#pragma unroll
                for (int t = 0; t < 16; t++) {
                    ulonglong2 vv = vrow[t];
                    o2[2 * t]     = fma2(rd, o2[2 * t],     vv.x);
                    o2[2 * t + 1] = fma2(rd, o2[2 * t + 1], vv.y);
                }
            }
        }
        __syncthreads();
    }

    float inv = 1.0f / lsum;
    u64 invd = pack_dup(inv);
    float* op = g_ctx + ((size_t)b * SEQ + qrow) * HIDDEN + h * HDIM;
#pragma unroll
    for (int t = 0; t < 16; t++) {
        float2 a = unpack2(fma2(invd, o2[2 * t], 0ull));
        float2 c = unpack2(fma2(invd, o2[2 * t + 1], 0ull));
        float4 o4 = make_float4(a.x, a.y, c.x, c.y);
        *(float4*)(op + 4 * t) = o4;
    }
}

// ============================================================================
// launcher — pure kernel launches, nothing else.
// ============================================================================
extern "C" void kernel_launch(void* const* d_in, const int* in_sizes, int n_in,
                              void* d_out, int out_size)
{
    (void)in_sizes; (void)n_in; (void)out_size;
    const float* x  = (const float*)d_in[0];
    const float* wq = (const float*)d_in[1];
    const float* bq = (const float*)d_in[2];
    const float* wk = (const float*)d_in[3];
    const float* bk = (const float*)d_in[4];
    const float* wv = (const float*)d_in[5];
    const float* bv = (const float*)d_in[6];
    const float* wo = (const float*)d_in[7];
    const float* bo = (const float*)d_in[8];
    float* out = (float*)d_out;

    dim3 ggrid(HIDDEN / 128, MROWS / 128);  // (8, 32)

    gemm_bias_kernel<0><<<ggrid, 256>>>(x, wq, bq, nullptr);  // -> g_q
    gemm_bias_kernel<1><<<ggrid, 256>>>(x, wk, bk, nullptr);  // -> g_k
    gemm_bias_kernel<2><<<ggrid, 256>>>(x, wv, bv, nullptr);  // -> g_v

    dim3 agrid(SEQ / 128, NHEADS, BATCH);   // (16, 16, 2)
    attn_kernel<<<agrid, 128>>>();          // g_q,g_k,g_v -> g_ctx

    gemm_bias_kernel<3><<<ggrid, 256>>>(nullptr, wo, bo, out);  // g_ctx -> out
}

// round 5
// speedup vs baseline: 3.1557x; 3.1557x over previous
#include <cuda_runtime.h>
#include <cstddef>
#include <cstdint>

#define HIDDEN 1024
#define SEQ    2048
#define BATCH  2
#define NHEADS 16
#define HDIM   64
#define MROWS  (BATCH * SEQ)   // 4096

// ---------------- scratch ----------------
__device__ float g_q[BATCH * SEQ * HIDDEN];
__device__ float g_k[BATCH * SEQ * HIDDEN];
__device__ float g_v[BATCH * SEQ * HIDDEN];
__device__ float g_ctx[BATCH * SEQ * HIDDEN];

// ---------------- helpers ----------------
__device__ __forceinline__ uint32_t f2tf(float f) {
    uint32_t r; asm("cvt.rna.tf32.f32 %0, %1;" : "=r"(r) : "f"(f)); return r;
}
__device__ __forceinline__ void mma_tf32(float d[4], const uint32_t a[4],
                                         const uint32_t b[2]) {
    asm("mma.sync.aligned.m16n8k8.row.col.f32.tf32.tf32.f32 "
        "{%0,%1,%2,%3}, {%4,%5,%6,%7}, {%8,%9}, {%0,%1,%2,%3};"
        : "+f"(d[0]), "+f"(d[1]), "+f"(d[2]), "+f"(d[3])
        : "r"(a[0]), "r"(a[1]), "r"(a[2]), "r"(a[3]), "r"(b[0]), "r"(b[1]));
}

// ============================================================================
// GEMM: C[M,N] = A[M,K] @ W[N,K]^T + bias.  tf32 mma.sync.
// BM=128 BN=128 BK=16, 256 threads, 8 warps (2 M x 4 N), warp tile 64x32.
// MODE: 0->C=g_q, 1->C=g_k, 2->C=g_v (A=param); 3: A=g_ctx, C=param.
// ============================================================================
template <int MODE>
__global__ __launch_bounds__(256, 2)
void gemm_tf32_kernel(const float* __restrict__ Ain, const float* __restrict__ W,
                      const float* __restrict__ bias, float* __restrict__ Cin)
{
    const float* __restrict__ A = (MODE == 3) ? (const float*)g_ctx : Ain;
    float* __restrict__ C =
        (MODE == 0) ? g_q : (MODE == 1) ? g_k : (MODE == 2) ? g_v : Cin;

    __shared__ uint32_t As[128][20];  // [m][k], pad 4
    __shared__ uint32_t Ws[128][20];  // [n][k], pad 4

    const int tid = threadIdx.x;
    const int wid = tid >> 5;
    const int lane = tid & 31;
    const int g = lane >> 2;       // 0..7
    const int q = lane & 3;        // 0..3
    const int wm = (wid & 1) * 64; // warp M offset
    const int wn = (wid >> 1) * 32;// warp N offset

    const int bm = blockIdx.y * 128;
    const int bn = blockIdx.x * 128;

    // staging mapping: 2 passes, row = p*64 + tid/4, colblock = tid&3
    const int srow = tid >> 2;
    const int sc4  = (tid & 3) * 4;

    float acc[4][4][4];  // [mt][nt][reg]
#pragma unroll
    for (int i = 0; i < 4; i++)
#pragma unroll
        for (int j = 0; j < 4; j++)
#pragma unroll
            for (int r = 0; r < 4; r++) acc[i][j][r] = 0.0f;

    // ---- stage tile 0 ----
    float4 pa0 = *(const float4*)&A[(size_t)(bm + srow) * HIDDEN + sc4];
    float4 pa1 = *(const float4*)&A[(size_t)(bm + 64 + srow) * HIDDEN + sc4];
    float4 pb0 = *(const float4*)&W[(size_t)(bn + srow) * HIDDEN + sc4];
    float4 pb1 = *(const float4*)&W[(size_t)(bn + 64 + srow) * HIDDEN + sc4];
    {
        uint4 ua0 = make_uint4(f2tf(pa0.x), f2tf(pa0.y), f2tf(pa0.z), f2tf(pa0.w));
        uint4 ua1 = make_uint4(f2tf(pa1.x), f2tf(pa1.y), f2tf(pa1.z), f2tf(pa1.w));
        uint4 ub0 = make_uint4(f2tf(pb0.x), f2tf(pb0.y), f2tf(pb0.z), f2tf(pb0.w));
        uint4 ub1 = make_uint4(f2tf(pb1.x), f2tf(pb1.y), f2tf(pb1.z), f2tf(pb1.w));
        *(uint4*)&As[srow][sc4]      = ua0;
        *(uint4*)&As[64 + srow][sc4] = ua1;
        *(uint4*)&Ws[srow][sc4]      = ub0;
        *(uint4*)&Ws[64 + srow][sc4] = ub1;
    }
    __syncthreads();

    for (int kb = 0; kb < HIDDEN / 16; kb++) {
        // prefetch next tile into regs
        if (kb < HIDDEN / 16 - 1) {
            int k0 = (kb + 1) * 16;
            pa0 = *(const float4*)&A[(size_t)(bm + srow) * HIDDEN + k0 + sc4];
            pa1 = *(const float4*)&A[(size_t)(bm + 64 + srow) * HIDDEN + k0 + sc4];
            pb0 = *(const float4*)&W[(size_t)(bn + srow) * HIDDEN + k0 + sc4];
            pb1 = *(const float4*)&W[(size_t)(bn + 64 + srow) * HIDDEN + k0 + sc4];
        }

#pragma unroll
        for (int ks = 0; ks < 2; ks++) {
            const int k8 = ks * 8;
            uint32_t af[4][4];
#pragma unroll
            for (int mt = 0; mt < 4; mt++) {
                int m0 = wm + mt * 16;
                af[mt][0] = As[m0 + g][k8 + q];
                af[mt][1] = As[m0 + 8 + g][k8 + q];
                af[mt][2] = As[m0 + g][k8 + q + 4];
                af[mt][3] = As[m0 + 8 + g][k8 + q + 4];
            }
            uint32_t bf[4][2];
#pragma unroll
            for (int nt = 0; nt < 4; nt++) {
                int n0 = wn + nt * 8;
                bf[nt][0] = Ws[n0 + g][k8 + q];
                bf[nt][1] = Ws[n0 + g][k8 + q + 4];
            }
#pragma unroll
            for (int mt = 0; mt < 4; mt++)
#pragma unroll
                for (int nt = 0; nt < 4; nt++)
                    mma_tf32(acc[mt][nt], af[mt], bf[nt]);
        }
        __syncthreads();
        if (kb < HIDDEN / 16 - 1) {
            uint4 ua0 = make_uint4(f2tf(pa0.x), f2tf(pa0.y), f2tf(pa0.z), f2tf(pa0.w));
            uint4 ua1 = make_uint4(f2tf(pa1.x), f2tf(pa1.y), f2tf(pa1.z), f2tf(pa1.w));
            uint4 ub0 = make_uint4(f2tf(pb0.x), f2tf(pb0.y), f2tf(pb0.z), f2tf(pb0.w));
            uint4 ub1 = make_uint4(f2tf(pb1.x), f2tf(pb1.y), f2tf(pb1.z), f2tf(pb1.w));
            *(uint4*)&As[srow][sc4]      = ua0;
            *(uint4*)&As[64 + srow][sc4] = ua1;
            *(uint4*)&Ws[srow][sc4]      = ub0;
            *(uint4*)&Ws[64 + srow][sc4] = ub1;
            __syncthreads();
        }
    }

    // ---- epilogue ----
#pragma unroll
    for (int nt = 0; nt < 4; nt++) {
        int col = bn + wn + nt * 8 + 2 * q;
        float2 bb = *(const float2*)&bias[col];
#pragma unroll
        for (int mt = 0; mt < 4; mt++) {
            int row0 = bm + wm + mt * 16 + g;
            float2 o0 = make_float2(acc[mt][nt][0] + bb.x, acc[mt][nt][1] + bb.y);
            float2 o1 = make_float2(acc[mt][nt][2] + bb.x, acc[mt][nt][3] + bb.y);
            *(float2*)&C[(size_t)row0 * HIDDEN + col]       = o0;
            *(float2*)&C[(size_t)(row0 + 8) * HIDDEN + col] = o1;
        }
    }
}

// ============================================================================
// Flash attention with tf32 mma.sync.
// CTA: 128 threads (4 warps), Q tile 64 rows (16/warp), K/V tile 64 keys.
// grid = (SEQ/64, NHEADS, BATCH)
// ============================================================================
__global__ __launch_bounds__(128)
void attn_tf32_kernel()
{
    __shared__ uint32_t KVs[64][68];  // K or V tile, [key][dim], pad 4
    __shared__ uint32_t Ps[64][68];   // P tile, [qrow][key], pad 4

    const int b = blockIdx.z;
    const int h = blockIdx.y;
    const int qb = blockIdx.x * 64;
    const int tid = threadIdx.x;
    const int wid = tid >> 5;
    const int lane = tid & 31;
    const int g = lane >> 2;
    const int q = lane & 3;
    const float scale = 0.125f;

    // staging mapping: 8 passes, key = p*8 + tid/16, colblock = tid&15
    const int skey = tid >> 4;        // 0..7
    const int sc4  = (tid & 15) * 4;  // 0..60

    const size_t hoff = (size_t)h * HDIM;
    const float* kb_g = g_k + ((size_t)b * SEQ) * HIDDEN + hoff;
    const float* vb_g = g_v + ((size_t)b * SEQ) * HIDDEN + hoff;

    // ---- Q fragments (register resident), pre-scaled ----
    const int qrow0 = qb + wid * 16 + g;
    uint32_t qf[8][4];
    {
        const float* qp0 = g_q + ((size_t)b * SEQ + qrow0) * HIDDEN + hoff;
        const float* qp1 = qp0 + 8 * HIDDEN;
#pragma unroll
        for (int t = 0; t < 8; t++) {
            qf[t][0] = f2tf(qp0[8 * t + q] * scale);
            qf[t][1] = f2tf(qp1[8 * t + q] * scale);
            qf[t][2] = f2tf(qp0[8 * t + q + 4] * scale);
            qf[t][3] = f2tf(qp1[8 * t + q + 4] * scale);
        }
    }

    float oacc[8][4];
#pragma unroll
    for (int u = 0; u < 8; u++)
#pragma unroll
        for (int r = 0; r < 4; r++) oacc[u][r] = 0.0f;
    float m0 = -1e30f, m1 = -1e30f, l0 = 0.0f, l1 = 0.0f;

    for (int kt = 0; kt < SEQ; kt += 64) {
        // ---- stage K tile ----
        __syncthreads();
#pragma unroll
        for (int p = 0; p < 8; p++) {
            int key = p * 8 + skey;
            float4 kv = *(const float4*)(kb_g + (size_t)(kt + key) * HIDDEN + sc4);
            *(uint4*)&KVs[key][sc4] =
                make_uint4(f2tf(kv.x), f2tf(kv.y), f2tf(kv.z), f2tf(kv.w));
        }
        __syncthreads();

        // ---- S = Q K^T ----
        float sacc[8][4];
#pragma unroll
        for (int u = 0; u < 8; u++) {
#pragma unroll
            for (int r = 0; r < 4; r++) sacc[u][r] = 0.0f;
#pragma unroll
            for (int t = 0; t < 8; t++) {
                uint32_t bf[2];
                bf[0] = KVs[8 * u + g][8 * t + q];
                bf[1] = KVs[8 * u + g][8 * t + q + 4];
                mma_tf32(sacc[u], qf[t], bf);
            }
        }

        // ---- online softmax ----
        float mt0 = -1e30f, mt1 = -1e30f;
#pragma unroll
        for (int u = 0; u < 8; u++) {
            mt0 = fmaxf(mt0, fmaxf(sacc[u][0], sacc[u][1]));
            mt1 = fmaxf(mt1, fmaxf(sacc[u][2], sacc[u][3]));
        }
        mt0 = fmaxf(mt0, __shfl_xor_sync(0xffffffff, mt0, 1));
        mt0 = fmaxf(mt0, __shfl_xor_sync(0xffffffff, mt0, 2));
        mt1 = fmaxf(mt1, __shfl_xor_sync(0xffffffff, mt1, 1));
        mt1 = fmaxf(mt1, __shfl_xor_sync(0xffffffff, mt1, 2));

        float m0n = fmaxf(m0, mt0);
        float m1n = fmaxf(m1, mt1);
        float f0 = __expf(m0 - m0n);
        float f1 = __expf(m1 - m1n);
        m0 = m0n; m1 = m1n;

        float lt0 = 0.0f, lt1 = 0.0f;
        const int prow0 = wid * 16 + g;
#pragma unroll
        for (int u = 0; u < 8; u++) {
            float p0 = __expf(sacc[u][0] - m0n);
            float p1 = __expf(sacc[u][1] - m0n);
            float p2 = __expf(sacc[u][2] - m1n);
            float p3 = __expf(sacc[u][3] - m1n);
            lt0 += p0 + p1;
            lt1 += p2 + p3;
            Ps[prow0][8 * u + 2 * q]         = f2tf(p0);
            Ps[prow0][8 * u + 2 * q + 1]     = f2tf(p1);
            Ps[prow0 + 8][8 * u + 2 * q]     = f2tf(p2);
            Ps[prow0 + 8][8 * u + 2 * q + 1] = f2tf(p3);
        }
        lt0 += __shfl_xor_sync(0xffffffff, lt0, 1);
        lt0 += __shfl_xor_sync(0xffffffff, lt0, 2);
        lt1 += __shfl_xor_sync(0xffffffff, lt1, 1);
        lt1 += __shfl_xor_sync(0xffffffff, lt1, 2);
        l0 = l0 * f0 + lt0;
        l1 = l1 * f1 + lt1;

        // rescale O
#pragma unroll
        for (int u = 0; u < 8; u++) {
            oacc[u][0] *= f0; oacc[u][1] *= f0;
            oacc[u][2] *= f1; oacc[u][3] *= f1;
        }
        __syncwarp();

        // ---- stage V tile (overwrite KVs) ----
        __syncthreads();
#pragma unroll
        for (int p = 0; p < 8; p++) {
            int key = p * 8 + skey;
            float4 vv = *(const float4*)(vb_g + (size_t)(kt + key) * HIDDEN + sc4);
            *(uint4*)&KVs[key][sc4] =
                make_uint4(f2tf(vv.x), f2tf(vv.y), f2tf(vv.z), f2tf(vv.w));
        }
        __syncthreads();

        // ---- O += P V ----
#pragma unroll
        for (int u = 0; u < 8; u++) {
#pragma unroll
            for (int t = 0; t < 8; t++) {
                uint32_t af[4], bf[2];
                af[0] = Ps[prow0][8 * t + q];
                af[1] = Ps[prow0 + 8][8 * t + q];
                af[2] = Ps[prow0][8 * t + q + 4];
                af[3] = Ps[prow0 + 8][8 * t + q + 4];
                bf[0] = KVs[8 * t + q][8 * u + g];
                bf[1] = KVs[8 * t + q + 4][8 * u + g];
                mma_tf32(oacc[u], af, bf);
            }
        }
    }

    // ---- write out ----
    float inv0 = 1.0f / l0;
    float inv1 = 1.0f / l1;
    float* op0 = g_ctx + ((size_t)b * SEQ + qrow0) * HIDDEN + hoff;
    float* op1 = op0 + 8 * HIDDEN;
#pragma unroll
    for (int u = 0; u < 8; u++) {
        int col = 8 * u + 2 * q;
        *(float2*)&op0[col] = make_float2(oacc[u][0] * inv0, oacc[u][1] * inv0);
        *(float2*)&op1[col] = make_float2(oacc[u][2] * inv1, oacc[u][3] * inv1);
    }
}

// ============================================================================
// launcher — pure kernel launches.
// ============================================================================
extern "C" void kernel_launch(void* const* d_in, const int* in_sizes, int n_in,
                              void* d_out, int out_size)
{
    (void)in_sizes; (void)n_in; (void)out_size;
    const float* x  = (const float*)d_in[0];
    const float* wq = (const float*)d_in[1];
    const float* bq = (const float*)d_in[2];
    const float* wk = (const float*)d_in[3];
    const float* bk = (const float*)d_in[4];
    const float* wv = (const float*)d_in[5];
    const float* bv = (const float*)d_in[6];
    const float* wo = (const float*)d_in[7];
    const float* bo = (const float*)d_in[8];
    float* out = (float*)d_out;

    dim3 ggrid(HIDDEN / 128, MROWS / 128);  // (8, 32)

    gemm_tf32_kernel<0><<<ggrid, 256>>>(x, wq, bq, nullptr);   // -> g_q
    gemm_tf32_kernel<1><<<ggrid, 256>>>(x, wk, bk, nullptr);   // -> g_k
    gemm_tf32_kernel<2><<<ggrid, 256>>>(x, wv, bv, nullptr);   // -> g_v

    dim3 agrid(SEQ / 64, NHEADS, BATCH);    // (32, 16, 2)
    attn_tf32_kernel<<<agrid, 128>>>();     // -> g_ctx

    gemm_tf32_kernel<3><<<ggrid, 256>>>(nullptr, wo, bo, out); // g_ctx -> out
}

// round 6
// speedup vs baseline: 3.2017x; 1.0146x over previous
#include <cuda_runtime.h>
#include <cstddef>
#include <cstdint>

#define HIDDEN 1024
#define SEQ    2048
#define BATCH  2
#define NHEADS 16
#define HDIM   64
#define MROWS  (BATCH * SEQ)   // 4096

// ---------------- scratch ----------------
__device__ float g_q[BATCH * SEQ * HIDDEN];
__device__ float g_k[BATCH * SEQ * HIDDEN];
__device__ float g_v[BATCH * SEQ * HIDDEN];
__device__ float g_ctx[BATCH * SEQ * HIDDEN];

// ---------------- helpers ----------------
__device__ __forceinline__ uint32_t f2tf(float f) {
    uint32_t r; asm("cvt.rna.tf32.f32 %0, %1;" : "=r"(r) : "f"(f)); return r;
}
__device__ __forceinline__ void mma_tf32(float d[4], const uint32_t a[4],
                                         const uint32_t b[2]) {
    asm("mma.sync.aligned.m16n8k8.row.col.f32.tf32.tf32.f32 "
        "{%0,%1,%2,%3}, {%4,%5,%6,%7}, {%8,%9}, {%0,%1,%2,%3};"
        : "+f"(d[0]), "+f"(d[1]), "+f"(d[2]), "+f"(d[3])
        : "r"(a[0]), "r"(a[1]), "r"(a[2]), "r"(a[3]), "r"(b[0]), "r"(b[1]));
}
__device__ __forceinline__ void cp16(uint32_t dst, const void* src) {
    asm volatile("cp.async.cg.shared.global [%0], [%1], 16;" :: "r"(dst), "l"(src));
}
__device__ __forceinline__ void cp_commit() {
    asm volatile("cp.async.commit_group;");
}
__device__ __forceinline__ void cp_wait0() {
    asm volatile("cp.async.wait_group 0;");
}

// ============================================================================
// GEMM: C[M,N] = A[M,K] @ W[N,K]^T + bias.  tf32 mma.sync. (unchanged from R5)
// ============================================================================
template <int MODE>
__global__ __launch_bounds__(256, 2)
void gemm_tf32_kernel(const float* __restrict__ Ain, const float* __restrict__ W,
                      const float* __restrict__ bias, float* __restrict__ Cin)
{
    const float* __restrict__ A = (MODE == 3) ? (const float*)g_ctx : Ain;
    float* __restrict__ C =
        (MODE == 0) ? g_q : (MODE == 1) ? g_k : (MODE == 2) ? g_v : Cin;

    __shared__ uint32_t As[128][20];
    __shared__ uint32_t Ws[128][20];

    const int tid = threadIdx.x;
    const int wid = tid >> 5;
    const int lane = tid & 31;
    const int g = lane >> 2;
    const int q = lane & 3;
    const int wm = (wid & 1) * 64;
    const int wn = (wid >> 1) * 32;

    const int bm = blockIdx.y * 128;
    const int bn = blockIdx.x * 128;

    const int srow = tid >> 2;
    const int sc4  = (tid & 3) * 4;

    float acc[4][4][4];
#pragma unroll
    for (int i = 0; i < 4; i++)
#pragma unroll
        for (int j = 0; j < 4; j++)
#pragma unroll
            for (int r = 0; r < 4; r++) acc[i][j][r] = 0.0f;

    float4 pa0 = *(const float4*)&A[(size_t)(bm + srow) * HIDDEN + sc4];
    float4 pa1 = *(const float4*)&A[(size_t)(bm + 64 + srow) * HIDDEN + sc4];
    float4 pb0 = *(const float4*)&W[(size_t)(bn + srow) * HIDDEN + sc4];
    float4 pb1 = *(const float4*)&W[(size_t)(bn + 64 + srow) * HIDDEN + sc4];
    {
        uint4 ua0 = make_uint4(f2tf(pa0.x), f2tf(pa0.y), f2tf(pa0.z), f2tf(pa0.w));
        uint4 ua1 = make_uint4(f2tf(pa1.x), f2tf(pa1.y), f2tf(pa1.z), f2tf(pa1.w));
        uint4 ub0 = make_uint4(f2tf(pb0.x), f2tf(pb0.y), f2tf(pb0.z), f2tf(pb0.w));
        uint4 ub1 = make_uint4(f2tf(pb1.x), f2tf(pb1.y), f2tf(pb1.z), f2tf(pb1.w));
        *(uint4*)&As[srow][sc4]      = ua0;
        *(uint4*)&As[64 + srow][sc4] = ua1;
        *(uint4*)&Ws[srow][sc4]      = ub0;
        *(uint4*)&Ws[64 + srow][sc4] = ub1;
    }
    __syncthreads();

    for (int kb = 0; kb < HIDDEN / 16; kb++) {
        if (kb < HIDDEN / 16 - 1) {
            int k0 = (kb + 1) * 16;
            pa0 = *(const float4*)&A[(size_t)(bm + srow) * HIDDEN + k0 + sc4];
            pa1 = *(const float4*)&A[(size_t)(bm + 64 + srow) * HIDDEN + k0 + sc4];
            pb0 = *(const float4*)&W[(size_t)(bn + srow) * HIDDEN + k0 + sc4];
            pb1 = *(const float4*)&W[(size_t)(bn + 64 + srow) * HIDDEN + k0 + sc4];
        }

#pragma unroll
        for (int ks = 0; ks < 2; ks++) {
            const int k8 = ks * 8;
            uint32_t af[4][4];
#pragma unroll
            for (int mt = 0; mt < 4; mt++) {
                int m0 = wm + mt * 16;
                af[mt][0] = As[m0 + g][k8 + q];
                af[mt][1] = As[m0 + 8 + g][k8 + q];
                af[mt][2] = As[m0 + g][k8 + q + 4];
                af[mt][3] = As[m0 + 8 + g][k8 + q + 4];
            }
            uint32_t bf[4][2];
#pragma unroll
            for (int nt = 0; nt < 4; nt++) {
                int n0 = wn + nt * 8;
                bf[nt][0] = Ws[n0 + g][k8 + q];
                bf[nt][1] = Ws[n0 + g][k8 + q + 4];
            }
#pragma unroll
            for (int mt = 0; mt < 4; mt++)
#pragma unroll
                for (int nt = 0; nt < 4; nt++)
                    mma_tf32(acc[mt][nt], af[mt], bf[nt]);
        }
        __syncthreads();
        if (kb < HIDDEN / 16 - 1) {
            uint4 ua0 = make_uint4(f2tf(pa0.x), f2tf(pa0.y), f2tf(pa0.z), f2tf(pa0.w));
            uint4 ua1 = make_uint4(f2tf(pa1.x), f2tf(pa1.y), f2tf(pa1.z), f2tf(pa1.w));
            uint4 ub0 = make_uint4(f2tf(pb0.x), f2tf(pb0.y), f2tf(pb0.z), f2tf(pb0.w));
            uint4 ub1 = make_uint4(f2tf(pb1.x), f2tf(pb1.y), f2tf(pb1.z), f2tf(pb1.w));
            *(uint4*)&As[srow][sc4]      = ua0;
            *(uint4*)&As[64 + srow][sc4] = ua1;
            *(uint4*)&Ws[srow][sc4]      = ub0;
            *(uint4*)&Ws[64 + srow][sc4] = ub1;
            __syncthreads();
        }
    }

#pragma unroll
    for (int nt = 0; nt < 4; nt++) {
        int col = bn + wn + nt * 8 + 2 * q;
        float2 bb = *(const float2*)&bias[col];
#pragma unroll
        for (int mt = 0; mt < 4; mt++) {
            int row0 = bm + wm + mt * 16 + g;
            float2 o0 = make_float2(acc[mt][nt][0] + bb.x, acc[mt][nt][1] + bb.y);
            float2 o1 = make_float2(acc[mt][nt][2] + bb.x, acc[mt][nt][3] + bb.y);
            *(float2*)&C[(size_t)row0 * HIDDEN + col]       = o0;
            *(float2*)&C[(size_t)(row0 + 8) * HIDDEN + col] = o1;
        }
    }
}

// ============================================================================
// Flash attention, tf32 mma, cp.async double-buffered K/V with XOR swizzle.
// Dynamic smem: Kbuf[2][64*64] | Vbuf[2][64*64] | Ps[64][68]  (~83 KB)
// K/V smem layout: word (row,col) at row*64 + 4*((col>>2) ^ (row&7)) + (col&3)
// grid = (SEQ/64, NHEADS, BATCH), 128 threads.
// ============================================================================
#define ATTN_SMEM (2 * 64 * 64 * 4 * 2 + 64 * 68 * 4)

__device__ __forceinline__ void stage_kv(uint32_t smK, uint32_t smV,
                                         const float* kb_g, const float* vb_g,
                                         int ktbase, int tid)
{
#pragma unroll
    for (int i = 0; i < 8; i++) {
        int id = i * 128 + tid;          // 0..1023
        int row = id >> 4;               // 0..63
        int c = id & 15;                 // chunk 0..15
        uint32_t doff = (uint32_t)(row * 256 + ((c ^ (row & 7)) << 4));
        const float* srcK = kb_g + (size_t)(ktbase + row) * HIDDEN + c * 4;
        const float* srcV = vb_g + (size_t)(ktbase + row) * HIDDEN + c * 4;
        cp16(smK + doff, srcK);
        cp16(smV + doff, srcV);
    }
}

__global__ __launch_bounds__(128)
void attn_tf32_kernel()
{
    extern __shared__ char dsm[];
    uint32_t* Kb = (uint32_t*)dsm;                     // [2][4096]
    uint32_t* Vb = (uint32_t*)(dsm + 32768);           // [2][4096]
    uint32_t (*Ps)[68] = (uint32_t(*)[68])(dsm + 65536);

    const uint32_t smem_u32 = (uint32_t)__cvta_generic_to_shared(dsm);
    const uint32_t smK_base = smem_u32;
    const uint32_t smV_base = smem_u32 + 32768;

    const int b = blockIdx.z;
    const int h = blockIdx.y;
    const int qb = blockIdx.x * 64;
    const int tid = threadIdx.x;
    const int wid = tid >> 5;
    const int lane = tid & 31;
    const int g = lane >> 2;
    const int q = lane & 3;
    const float scale = 0.125f;

    const size_t hoff = (size_t)h * HDIM;
    const float* kb_g = g_k + ((size_t)b * SEQ) * HIDDEN + hoff;
    const float* vb_g = g_v + ((size_t)b * SEQ) * HIDDEN + hoff;

    // prologue: stage tile 0
    stage_kv(smK_base, smV_base, kb_g, vb_g, 0, tid);
    cp_commit();

    // Q fragments, register resident, RNA-rounded + pre-scaled
    const int qrow0 = qb + wid * 16 + g;
    uint32_t qf[8][4];
    {
        const float* qp0 = g_q + ((size_t)b * SEQ + qrow0) * HIDDEN + hoff;
        const float* qp1 = qp0 + 8 * HIDDEN;
#pragma unroll
        for (int t = 0; t < 8; t++) {
            qf[t][0] = f2tf(qp0[8 * t + q] * scale);
            qf[t][1] = f2tf(qp1[8 * t + q] * scale);
            qf[t][2] = f2tf(qp0[8 * t + q + 4] * scale);
            qf[t][3] = f2tf(qp1[8 * t + q + 4] * scale);
        }
    }

    float oacc[8][4];
#pragma unroll
    for (int u = 0; u < 8; u++)
#pragma unroll
        for (int r = 0; r < 4; r++) oacc[u][r] = 0.0f;
    float m0 = -1e30f, m1 = -1e30f, l0 = 0.0f, l1 = 0.0f;

    const int prow0 = wid * 16 + g;

    for (int it = 0; it < SEQ / 64; it++) {
        const int cur = it & 1;
        cp_wait0();
        __syncthreads();
        if (it + 1 < SEQ / 64) {
            stage_kv(smK_base + (cur ^ 1) * 16384, smV_base + (cur ^ 1) * 16384,
                     kb_g, vb_g, (it + 1) * 64, tid);
            cp_commit();
        }

        const uint32_t* __restrict__ K = Kb + cur * 4096;
        const uint32_t* __restrict__ V = Vb + cur * 4096;

        // ---- S = Q K^T ----
        float sacc[8][4];
#pragma unroll
        for (int u = 0; u < 8; u++) {
#pragma unroll
            for (int r = 0; r < 4; r++) sacc[u][r] = 0.0f;
            const int krow = (8 * u + g) * 64;
#pragma unroll
            for (int t = 0; t < 8; t++) {
                uint32_t bf[2];
                bf[0] = K[krow + 4 * ((2 * t) ^ g) + q];
                bf[1] = K[krow + 4 * ((2 * t + 1) ^ g) + q];
                mma_tf32(sacc[u], qf[t], bf);
            }
        }

        // ---- online softmax ----
        float mt0 = -1e30f, mt1 = -1e30f;
#pragma unroll
        for (int u = 0; u < 8; u++) {
            mt0 = fmaxf(mt0, fmaxf(sacc[u][0], sacc[u][1]));
            mt1 = fmaxf(mt1, fmaxf(sacc[u][2], sacc[u][3]));
        }
        mt0 = fmaxf(mt0, __shfl_xor_sync(0xffffffff, mt0, 1));
        mt0 = fmaxf(mt0, __shfl_xor_sync(0xffffffff, mt0, 2));
        mt1 = fmaxf(mt1, __shfl_xor_sync(0xffffffff, mt1, 1));
        mt1 = fmaxf(mt1, __shfl_xor_sync(0xffffffff, mt1, 2));

        float m0n = fmaxf(m0, mt0);
        float m1n = fmaxf(m1, mt1);
        float f0 = __expf(m0 - m0n);
        float f1 = __expf(m1 - m1n);
        m0 = m0n; m1 = m1n;

        float lt0 = 0.0f, lt1 = 0.0f;
#pragma unroll
        for (int u = 0; u < 8; u++) {
            float p0 = __expf(sacc[u][0] - m0n);
            float p1 = __expf(sacc[u][1] - m0n);
            float p2 = __expf(sacc[u][2] - m1n);
            float p3 = __expf(sacc[u][3] - m1n);
            lt0 += p0 + p1;
            lt1 += p2 + p3;
            Ps[prow0][8 * u + 2 * q]         = f2tf(p0);
            Ps[prow0][8 * u + 2 * q + 1]     = f2tf(p1);
            Ps[prow0 + 8][8 * u + 2 * q]     = f2tf(p2);
            Ps[prow0 + 8][8 * u + 2 * q + 1] = f2tf(p3);
        }
        lt0 += __shfl_xor_sync(0xffffffff, lt0, 1);
        lt0 += __shfl_xor_sync(0xffffffff, lt0, 2);
        lt1 += __shfl_xor_sync(0xffffffff, lt1, 1);
        lt1 += __shfl_xor_sync(0xffffffff, lt1, 2);
        l0 = l0 * f0 + lt0;
        l1 = l1 * f1 + lt1;

#pragma unroll
        for (int u = 0; u < 8; u++) {
            oacc[u][0] *= f0; oacc[u][1] *= f0;
            oacc[u][2] *= f1; oacc[u][3] *= f1;
        }
        __syncwarp();

        // ---- O += P V   (t outer: af loaded once per t, reused across u) ----
#pragma unroll
        for (int t = 0; t < 8; t++) {
            uint32_t af[4];
            af[0] = Ps[prow0][8 * t + q];
            af[1] = Ps[prow0 + 8][8 * t + q];
            af[2] = Ps[prow0][8 * t + q + 4];
            af[3] = Ps[prow0 + 8][8 * t + q + 4];
            const int vr0 = (8 * t + q) * 64;
            const int vr1 = (8 * t + q + 4) * 64;
            const int g2 = g >> 2;       // 0/1
            const int gw = g & 3;        // word in chunk
#pragma unroll
            for (int u = 0; u < 8; u++) {
                uint32_t bf[2];
                bf[0] = V[vr0 + 4 * ((2 * u + g2) ^ q) + gw];
                bf[1] = V[vr1 + 4 * ((2 * u + g2) ^ (q + 4)) + gw];
                mma_tf32(oacc[u], af, bf);
            }
        }
    }

    // ---- write out ----
    float inv0 = 1.0f / l0;
    float inv1 = 1.0f / l1;
    float* op0 = g_ctx + ((size_t)b * SEQ + qrow0) * HIDDEN + hoff;
    float* op1 = op0 + 8 * HIDDEN;
#pragma unroll
    for (int u = 0; u < 8; u++) {
        int col = 8 * u + 2 * q;
        *(float2*)&op0[col] = make_float2(oacc[u][0] * inv0, oacc[u][1] * inv0);
        *(float2*)&op1[col] = make_float2(oacc[u][2] * inv1, oacc[u][3] * inv1);
    }
}

// ============================================================================
// launcher
// ============================================================================
extern "C" void kernel_launch(void* const* d_in, const int* in_sizes, int n_in,
                              void* d_out, int out_size)
{
    (void)in_sizes; (void)n_in; (void)out_size;
    const float* x  = (const float*)d_in[0];
    const float* wq = (const float*)d_in[1];
    const float* bq = (const float*)d_in[2];
    const float* wk = (const float*)d_in[3];
    const float* bk = (const float*)d_in[4];
    const float* wv = (const float*)d_in[5];
    const float* bv = (const float*)d_in[6];
    const float* wo = (const float*)d_in[7];
    const float* bo = (const float*)d_in[8];
    float* out = (float*)d_out;

    static bool attr_set = false;
    if (!attr_set) {
        cudaFuncSetAttribute(attn_tf32_kernel,
                             cudaFuncAttributeMaxDynamicSharedMemorySize, ATTN_SMEM);
        attr_set = true;
    }

    dim3 ggrid(HIDDEN / 128, MROWS / 128);  // (8, 32)

    gemm_tf32_kernel<0><<<ggrid, 256>>>(x, wq, bq, nullptr);   // -> g_q
    gemm_tf32_kernel<1><<<ggrid, 256>>>(x, wk, bk, nullptr);   // -> g_k
    gemm_tf32_kernel<2><<<ggrid, 256>>>(x, wv, bv, nullptr);   // -> g_v

    dim3 agrid(SEQ / 64, NHEADS, BATCH);    // (32, 16, 2)
    attn_tf32_kernel<<<agrid, 128, ATTN_SMEM>>>();             // -> g_ctx

    gemm_tf32_kernel<3><<<ggrid, 256>>>(nullptr, wo, bo, out); // g_ctx -> out
}

// round 11
// speedup vs baseline: 5.3281x; 1.6641x over previous
#include <cuda_runtime.h>
#include <cuda_fp16.h>
#include <cstddef>
#include <cstdint>
#include <cstring>

#define HIDDEN 1024
#define SEQ    2048
#define BATCH  2
#define NHEADS 16
#define HDIM   64
#define MROWS  (BATCH * SEQ)   // 4096

// ---------------- scratch (fp16, force 16B+ alignment for uint4/cp.async) ----
__device__ __align__(256) __half g_q[BATCH * SEQ * HIDDEN];
__device__ __align__(256) __half g_k[BATCH * SEQ * HIDDEN];
__device__ __align__(256) __half g_v[BATCH * SEQ * HIDDEN];
__device__ __align__(256) __half g_ctx[BATCH * SEQ * HIDDEN];

// ---------------- helpers ----------------
__device__ __forceinline__ uint32_t fpack2(float a, float b) {
    __half2 h = __floats2half2_rn(a, b);
    uint32_t u; memcpy(&u, &h, 4); return u;
}
__device__ __forceinline__ uint32_t hmul2u(uint32_t a, uint32_t s) {
    __half2 ha, hs; memcpy(&ha, &a, 4); memcpy(&hs, &s, 4);
    __half2 r = __hmul2(ha, hs);
    uint32_t u; memcpy(&u, &r, 4); return u;
}
__device__ __forceinline__ void mma_f16(float d[4], const uint32_t a[4],
                                        uint32_t b0, uint32_t b1) {
    asm("mma.sync.aligned.m16n8k16.row.col.f32.f16.f16.f32 "
        "{%0,%1,%2,%3}, {%4,%5,%6,%7}, {%8,%9}, {%0,%1,%2,%3};"
        : "+f"(d[0]), "+f"(d[1]), "+f"(d[2]), "+f"(d[3])
        : "r"(a[0]), "r"(a[1]), "r"(a[2]), "r"(a[3]), "r"(b0), "r"(b1));
}
__device__ __forceinline__ void ldm_x4_t(uint32_t& r0, uint32_t& r1,
                                         uint32_t& r2, uint32_t& r3, uint32_t addr) {
    asm volatile("ldmatrix.sync.aligned.m8n8.x4.trans.shared.b16 {%0,%1,%2,%3}, [%4];"
                 : "=r"(r0), "=r"(r1), "=r"(r2), "=r"(r3) : "r"(addr));
}
__device__ __forceinline__ void cp16(uint32_t dst, const void* src) {
    asm volatile("cp.async.cg.shared.global [%0], [%1], 16;" :: "r"(dst), "l"(src));
}
__device__ __forceinline__ void cp_commit() { asm volatile("cp.async.commit_group;"); }
__device__ __forceinline__ void cp_wait0()  { asm volatile("cp.async.wait_group 0;"); }
__device__ __forceinline__ uint32_t cvta_sh(const void* p) {
    return (uint32_t)__cvta_generic_to_shared(p);
}

// ============================================================================
// fp16 GEMM: C[M,N] = A[M,K] @ W[N,K]^T + bias[N]
// BM=128 BN=128 BK=32, 256 threads, 8 warps (2Mx4N), warp tile 64x32, m16n8k16.
// Row pad = 20 words (80 B): 16B-aligned uint4 rows AND conflict-free frag reads.
// MODE 0/1/2: A = f32 param, C = g_q/g_k/g_v (fp16).  MODE 3: A = g_ctx (fp16),
// C = f32 param.
// ============================================================================
template <int MODE>
__global__ __launch_bounds__(256, 2)
void gemm_h_kernel(const float* __restrict__ Ain, const float* __restrict__ W,
                   const float* __restrict__ bias, float* __restrict__ Cout)
{
    __shared__ uint32_t As[128][20];   // [m][kword], fp16x2 words
    __shared__ uint32_t Ws[128][20];   // [n][kword]

    const int tid = threadIdx.x;
    const int wid = tid >> 5;
    const int lane = tid & 31;
    const int g = lane >> 2;
    const int q = lane & 3;
    const int wm = (wid & 1) * 64;
    const int wn = (wid >> 1) * 32;
    const int bm = blockIdx.y * 128;
    const int bn = blockIdx.x * 128;

    const int srow = tid >> 1;        // 0..127
    const int sh   = (tid & 1) * 8;   // word offset 0/8 (floats 0/16)

    float acc[4][4][4];
#pragma unroll
    for (int i = 0; i < 4; i++)
#pragma unroll
        for (int j = 0; j < 4; j++)
#pragma unroll
            for (int r = 0; r < 4; r++) acc[i][j][r] = 0.0f;

    float4 wa[4], aa[4];
    uint4  ah[2];

    // ---- load chunk 0 ----
#pragma unroll
    for (int j = 0; j < 4; j++)
        wa[j] = *(const float4*)&W[(size_t)(bn + srow) * HIDDEN + sh * 2 + j * 4];
    if (MODE < 3) {
#pragma unroll
        for (int j = 0; j < 4; j++)
            aa[j] = *(const float4*)&Ain[(size_t)(bm + srow) * HIDDEN + sh * 2 + j * 4];
    } else {
        const uint4* ap = (const uint4*)((const uint32_t*)g_ctx +
                                         (size_t)(bm + srow) * 512 + sh);
        ah[0] = ap[0]; ah[1] = ap[1];
    }
    // ---- store chunk 0 ----
#pragma unroll
    for (int j = 0; j < 4; j++) {
        Ws[srow][sh + 2 * j]     = fpack2(wa[j].x, wa[j].y);
        Ws[srow][sh + 2 * j + 1] = fpack2(wa[j].z, wa[j].w);
    }
    if (MODE < 3) {
#pragma unroll
        for (int j = 0; j < 4; j++) {
            As[srow][sh + 2 * j]     = fpack2(aa[j].x, aa[j].y);
            As[srow][sh + 2 * j + 1] = fpack2(aa[j].z, aa[j].w);
        }
    } else {
        *(uint4*)&As[srow][sh]     = ah[0];
        *(uint4*)&As[srow][sh + 4] = ah[1];
    }
    __syncthreads();

    for (int kb = 0; kb < 32; kb++) {
        // prefetch next chunk
        if (kb < 31) {
            int f0 = (kb + 1) * 32 + sh * 2;
#pragma unroll
            for (int j = 0; j < 4; j++)
                wa[j] = *(const float4*)&W[(size_t)(bn + srow) * HIDDEN + f0 + j * 4];
            if (MODE < 3) {
#pragma unroll
                for (int j = 0; j < 4; j++)
                    aa[j] = *(const float4*)&Ain[(size_t)(bm + srow) * HIDDEN + f0 + j * 4];
            } else {
                const uint4* ap = (const uint4*)((const uint32_t*)g_ctx +
                                                 (size_t)(bm + srow) * 512 +
                                                 (kb + 1) * 16 + sh);
                ah[0] = ap[0]; ah[1] = ap[1];
            }
        }

#pragma unroll
        for (int ks = 0; ks < 2; ks++) {
            const int kw = ks * 8;
            uint32_t af[4][4];
#pragma unroll
            for (int mt = 0; mt < 4; mt++) {
                int m0 = wm + mt * 16;
                af[mt][0] = As[m0 + g][kw + q];
                af[mt][1] = As[m0 + 8 + g][kw + q];
                af[mt][2] = As[m0 + g][kw + q + 4];
                af[mt][3] = As[m0 + 8 + g][kw + q + 4];
            }
            uint32_t bf[4][2];
#pragma unroll
            for (int nt = 0; nt < 4; nt++) {
                int n0 = wn + nt * 8;
                bf[nt][0] = Ws[n0 + g][kw + q];
                bf[nt][1] = Ws[n0 + g][kw + q + 4];
            }
#pragma unroll
            for (int mt = 0; mt < 4; mt++)
#pragma unroll
                for (int nt = 0; nt < 4; nt++)
                    mma_f16(acc[mt][nt], af[mt], bf[nt][0], bf[nt][1]);
        }
        __syncthreads();
        if (kb < 31) {
#pragma unroll
            for (int j = 0; j < 4; j++) {
                Ws[srow][sh + 2 * j]     = fpack2(wa[j].x, wa[j].y);
                Ws[srow][sh + 2 * j + 1] = fpack2(wa[j].z, wa[j].w);
            }
            if (MODE < 3) {
#pragma unroll
                for (int j = 0; j < 4; j++) {
                    As[srow][sh + 2 * j]     = fpack2(aa[j].x, aa[j].y);
                    As[srow][sh + 2 * j + 1] = fpack2(aa[j].z, aa[j].w);
                }
            } else {
                *(uint4*)&As[srow][sh]     = ah[0];
                *(uint4*)&As[srow][sh + 4] = ah[1];
            }
            __syncthreads();
        }
    }

    // ---- epilogue ----
    if (MODE < 3) {
        __half* Ch = (MODE == 0) ? g_q : (MODE == 1) ? g_k : g_v;
        uint32_t* C32 = (uint32_t*)Ch;
#pragma unroll
        for (int nt = 0; nt < 4; nt++) {
            int col = bn + wn + nt * 8 + 2 * q;
            float2 bb = *(const float2*)&bias[col];
            int colw = col >> 1;   // col even
#pragma unroll
            for (int mt = 0; mt < 4; mt++) {
                int row0 = bm + wm + mt * 16 + g;
                C32[(size_t)row0 * 512 + colw] =
                    fpack2(acc[mt][nt][0] + bb.x, acc[mt][nt][1] + bb.y);
                C32[(size_t)(row0 + 8) * 512 + colw] =
                    fpack2(acc[mt][nt][2] + bb.x, acc[mt][nt][3] + bb.y);
            }
        }
    } else {
#pragma unroll
        for (int nt = 0; nt < 4; nt++) {
            int col = bn + wn + nt * 8 + 2 * q;
            float2 bb = *(const float2*)&bias[col];
#pragma unroll
            for (int mt = 0; mt < 4; mt++) {
                int row0 = bm + wm + mt * 16 + g;
                *(float2*)&Cout[(size_t)row0 * HIDDEN + col] =
                    make_float2(acc[mt][nt][0] + bb.x, acc[mt][nt][1] + bb.y);
                *(float2*)&Cout[(size_t)(row0 + 8) * HIDDEN + col] =
                    make_float2(acc[mt][nt][2] + bb.x, acc[mt][nt][3] + bb.y);
            }
        }
    }
}

// ============================================================================
// Flash attention, fp16 mma (m16n8k16), cp.async double-buffered fp16 K/V,
// ldmatrix.x4.trans for V B-fragments.  Static smem ~41 KB.
// CTA: 128 threads (4 warps), Q tile 64 rows, K/V tile 64 keys.
// grid = (SEQ/64, NHEADS, BATCH)
// ============================================================================
__global__ __launch_bounds__(128)
void attn_h_kernel()
{
    __shared__ uint32_t Kw[2][64 * 32];   // fp16x2 words, XOR-swizzled rows
    __shared__ uint32_t Vw[2][64 * 32];
    __shared__ uint32_t Ps[64][36];       // P tile fp16x2, pad 4

    const int b = blockIdx.z;
    const int h = blockIdx.y;
    const int qb = blockIdx.x * 64;
    const int tid = threadIdx.x;
    const int wid = tid >> 5;
    const int lane = tid & 31;
    const int g = lane >> 2;
    const int q = lane & 3;

    const __half* kb_g = g_k + ((size_t)b * SEQ) * HIDDEN + h * HDIM;
    const __half* vb_g = g_v + ((size_t)b * SEQ) * HIDDEN + h * HDIM;
    const uint32_t smK[2] = { cvta_sh(Kw[0]), cvta_sh(Kw[1]) };
    const uint32_t smV[2] = { cvta_sh(Vw[0]), cvta_sh(Vw[1]) };

    // stage K/V tile: 64 rows x 8 chunks(16B); 4 K + 4 V chunks per thread
    auto stage = [&](int buf, int ktbase) {
#pragma unroll
        for (int i = 0; i < 4; i++) {
            int id = i * 128 + tid;       // 0..511
            int row = id >> 3;            // 0..63
            int c = id & 7;               // chunk
            uint32_t doff = (uint32_t)(row * 128 + ((c ^ (row & 7)) << 4));
            cp16(smK[buf] + doff, kb_g + (size_t)(ktbase + row) * HIDDEN + c * 8);
            cp16(smV[buf] + doff, vb_g + (size_t)(ktbase + row) * HIDDEN + c * 8);
        }
    };

    stage(0, 0);
    cp_commit();

    // ---- Q fragments (fp16, register resident), scaled by 1/8 ----
    const int qrow0 = qb + wid * 16 + g;
    const uint32_t qs = fpack2(0.125f, 0.125f);
    uint32_t qf[4][4];
    {
        const uint32_t* qp0 = (const uint32_t*)g_q +
                              ((size_t)b * SEQ + qrow0) * 512 + h * 32;
        const uint32_t* qp1 = qp0 + 8 * 512;
#pragma unroll
        for (int t = 0; t < 4; t++) {
            qf[t][0] = hmul2u(qp0[8 * t + q], qs);
            qf[t][1] = hmul2u(qp1[8 * t + q], qs);
            qf[t][2] = hmul2u(qp0[8 * t + q + 4], qs);
            qf[t][3] = hmul2u(qp1[8 * t + q + 4], qs);
        }
    }

    float oacc[8][4];
#pragma unroll
    for (int u = 0; u < 8; u++)
#pragma unroll
        for (int r = 0; r < 4; r++) oacc[u][r] = 0.0f;
    float m0 = -1e30f, m1 = -1e30f, l0 = 0.0f, l1 = 0.0f;

    const int prow0 = wid * 16 + g;

    for (int it = 0; it < SEQ / 64; it++) {
        const int cur = it & 1;
        cp_wait0();
        __syncthreads();
        if (it + 1 < SEQ / 64) {
            stage(cur ^ 1, (it + 1) * 64);
            cp_commit();
        }

        const uint32_t* __restrict__ K = Kw[cur];

        // ---- S = Q K^T ----
        float sacc[8][4];
#pragma unroll
        for (int u = 0; u < 8; u++) {
#pragma unroll
            for (int r = 0; r < 4; r++) sacc[u][r] = 0.0f;
            const uint32_t* kr = K + (8 * u + g) * 32;
#pragma unroll
            for (int t = 0; t < 4; t++) {
                uint32_t b0 = kr[4 * ((2 * t) ^ g) + q];
                uint32_t b1 = kr[4 * ((2 * t + 1) ^ g) + q];
                mma_f16(sacc[u], qf[t], b0, b1);
            }
        }

        // ---- online softmax ----
        float mt0 = -1e30f, mt1 = -1e30f;
#pragma unroll
        for (int u = 0; u < 8; u++) {
            mt0 = fmaxf(mt0, fmaxf(sacc[u][0], sacc[u][1]));
            mt1 = fmaxf(mt1, fmaxf(sacc[u][2], sacc[u][3]));
        }
        mt0 = fmaxf(mt0, __shfl_xor_sync(0xffffffff, mt0, 1));
        mt0 = fmaxf(mt0, __shfl_xor_sync(0xffffffff, mt0, 2));
        mt1 = fmaxf(mt1, __shfl_xor_sync(0xffffffff, mt1, 1));
        mt1 = fmaxf(mt1, __shfl_xor_sync(0xffffffff, mt1, 2));

        float m0n = fmaxf(m0, mt0);
        float m1n = fmaxf(m1, mt1);
        float f0 = __expf(m0 - m0n);
        float f1 = __expf(m1 - m1n);
        m0 = m0n; m1 = m1n;

        float lt0 = 0.0f, lt1 = 0.0f;
#pragma unroll
        for (int u = 0; u < 8; u++) {
            float p0 = __expf(sacc[u][0] - m0n);
            float p1 = __expf(sacc[u][1] - m0n);
            float p2 = __expf(sacc[u][2] - m1n);
            float p3 = __expf(sacc[u][3] - m1n);
            lt0 += p0 + p1;
            lt1 += p2 + p3;
            Ps[prow0][4 * u + q]     = fpack2(p0, p1);
            Ps[prow0 + 8][4 * u + q] = fpack2(p2, p3);
        }
        lt0 += __shfl_xor_sync(0xffffffff, lt0, 1);
        lt0 += __shfl_xor_sync(0xffffffff, lt0, 2);
        lt1 += __shfl_xor_sync(0xffffffff, lt1, 1);
        lt1 += __shfl_xor_sync(0xffffffff, lt1, 2);
        l0 = l0 * f0 + lt0;
        l1 = l1 * f1 + lt1;

#pragma unroll
        for (int u = 0; u < 8; u++) {
            oacc[u][0] *= f0; oacc[u][1] *= f0;
            oacc[u][2] *= f1; oacc[u][3] *= f1;
        }
        __syncwarp();

        // ---- O += P V  (V B-frags via ldmatrix.x4.trans) ----
        const int mat = lane >> 3;          // 0..3
        const int mrow = lane & 7;
#pragma unroll
        for (int t = 0; t < 4; t++) {
            uint32_t af[4];
            af[0] = Ps[prow0][8 * t + q];
            af[1] = Ps[prow0 + 8][8 * t + q];
            af[2] = Ps[prow0][8 * t + q + 4];
            af[3] = Ps[prow0 + 8][8 * t + q + 4];
#pragma unroll
            for (int u2 = 0; u2 < 4; u2++) {
                int key = 16 * t + (mat & 1) * 8 + mrow;
                int cn  = 2 * u2 + (mat >> 1);
                uint32_t addr = smV[cur] + key * 128 + ((cn ^ (key & 7)) << 4);
                uint32_t b0, b1, b2, b3;
                ldm_x4_t(b0, b1, b2, b3, addr);
                mma_f16(oacc[2 * u2], af, b0, b1);
                mma_f16(oacc[2 * u2 + 1], af, b2, b3);
            }
        }
    }

    // ---- write ctx as fp16 ----
    float inv0 = 1.0f / l0;
    float inv1 = 1.0f / l1;
    uint32_t* op0 = (uint32_t*)g_ctx + ((size_t)b * SEQ + qrow0) * 512 + h * 32;
    uint32_t* op1 = op0 + 8 * 512;
#pragma unroll
    for (int u = 0; u < 8; u++) {
        op0[4 * u + q] = fpack2(oacc[u][0] * inv0, oacc[u][1] * inv0);
        op1[4 * u + q] = fpack2(oacc[u][2] * inv1, oacc[u][3] * inv1);
    }
}

// ============================================================================
// launcher — pure kernel launches.
// ============================================================================
extern "C" void kernel_launch(void* const* d_in, const int* in_sizes, int n_in,
                              void* d_out, int out_size)
{
    (void)in_sizes; (void)n_in; (void)out_size;
    const float* x  = (const float*)d_in[0];
    const float* wq = (const float*)d_in[1];
    const float* bq = (const float*)d_in[2];
    const float* wk = (const float*)d_in[3];
    const float* bk = (const float*)d_in[4];
    const float* wv = (const float*)d_in[5];
    const float* bv = (const float*)d_in[6];
    const float* wo = (const float*)d_in[7];
    const float* bo = (const float*)d_in[8];
    float* out = (float*)d_out;

    dim3 ggrid(HIDDEN / 128, MROWS / 128);  // (8, 32)

    gemm_h_kernel<0><<<ggrid, 256>>>(x, wq, bq, nullptr);   // -> g_q (fp16)
    gemm_h_kernel<1><<<ggrid, 256>>>(x, wk, bk, nullptr);   // -> g_k
    gemm_h_kernel<2><<<ggrid, 256>>>(x, wv, bv, nullptr);   // -> g_v

    dim3 agrid(SEQ / 64, NHEADS, BATCH);    // (32, 16, 2)
    attn_h_kernel<<<agrid, 128>>>();        // -> g_ctx (fp16)

    gemm_h_kernel<3><<<ggrid, 256>>>(nullptr, wo, bo, out); // g_ctx -> out (f32)
}

// round 13
// speedup vs baseline: 7.4128x; 1.3913x over previous
#include <cuda_runtime.h>
#include <cuda_fp16.h>
#include <cstddef>
#include <cstdint>
#include <cstring>

#define HIDDEN 1024
#define SEQ    2048
#define BATCH  2
#define NHEADS 16
#define HDIM   64
#define MROWS  (BATCH * SEQ)   // 4096

// ---------------- scratch (fp16) ----------------
__device__ __align__(256) __half g_x [MROWS * HIDDEN];
__device__ __align__(256) __half g_wq[HIDDEN * HIDDEN];
__device__ __align__(256) __half g_wk[HIDDEN * HIDDEN];
__device__ __align__(256) __half g_wv[HIDDEN * HIDDEN];
__device__ __align__(256) __half g_wo[HIDDEN * HIDDEN];
__device__ __align__(256) __half g_q[BATCH * SEQ * HIDDEN];
__device__ __align__(256) __half g_k[BATCH * SEQ * HIDDEN];
__device__ __align__(256) __half g_v[BATCH * SEQ * HIDDEN];
__device__ __align__(256) __half g_ctx[BATCH * SEQ * HIDDEN];

// ---------------- helpers ----------------
__device__ __forceinline__ uint32_t fpack2(float a, float b) {
    __half2 h = __floats2half2_rn(a, b);
    uint32_t u; memcpy(&u, &h, 4); return u;
}
__device__ __forceinline__ uint32_t hmul2u(uint32_t a, uint32_t s) {
    __half2 ha, hs; memcpy(&ha, &a, 4); memcpy(&hs, &s, 4);
    __half2 r = __hmul2(ha, hs);
    uint32_t u; memcpy(&u, &r, 4); return u;
}
__device__ __forceinline__ void mma_f16(float d[4], const uint32_t a[4],
                                        uint32_t b0, uint32_t b1) {
    asm("mma.sync.aligned.m16n8k16.row.col.f32.f16.f16.f32 "
        "{%0,%1,%2,%3}, {%4,%5,%6,%7}, {%8,%9}, {%0,%1,%2,%3};"
        : "+f"(d[0]), "+f"(d[1]), "+f"(d[2]), "+f"(d[3])
        : "r"(a[0]), "r"(a[1]), "r"(a[2]), "r"(a[3]), "r"(b0), "r"(b1));
}
__device__ __forceinline__ void ldm_x4_t(uint32_t& r0, uint32_t& r1,
                                         uint32_t& r2, uint32_t& r3, uint32_t addr) {
    asm volatile("ldmatrix.sync.aligned.m8n8.x4.trans.shared.b16 {%0,%1,%2,%3}, [%4];"
                 : "=r"(r0), "=r"(r1), "=r"(r2), "=r"(r3) : "r"(addr));
}
__device__ __forceinline__ void cp16(uint32_t dst, const void* src) {
    asm volatile("cp.async.cg.shared.global [%0], [%1], 16;" :: "r"(dst), "l"(src));
}
__device__ __forceinline__ void cp_commit() { asm volatile("cp.async.commit_group;"); }
__device__ __forceinline__ void cp_wait0()  { asm volatile("cp.async.wait_group 0;"); }
__device__ __forceinline__ void cp_wait1()  { asm volatile("cp.async.wait_group 1;"); }
__device__ __forceinline__ uint32_t cvta_sh(const void* p) {
    return (uint32_t)__cvta_generic_to_shared(p);
}

// ============================================================================
// Fused prep: convert x + all 4 weight matrices f32 -> f16 in ONE launch.
// Flat groups of 8 floats. x: 524288 groups; each W: 131072 groups.
// ============================================================================
#define NX8 (MROWS * HIDDEN / 8)    // 524288
#define NW8 (HIDDEN * HIDDEN / 8)   // 131072
#define NPREP (NX8 + 4 * NW8)       // 1048576

__global__ __launch_bounds__(256)
void prep_kernel(const float* __restrict__ x,
                 const float* __restrict__ wq, const float* __restrict__ wk,
                 const float* __restrict__ wv, const float* __restrict__ wo)
{
    int i = blockIdx.x * blockDim.x + threadIdx.x;
    if (i >= NPREP) return;
    const float* src;
    __half* dst;
    int idx;
    if (i < NX8) {
        src = x; dst = g_x; idx = i;
    } else {
        int j = i - NX8;
        int w = j >> 17;            // / NW8
        idx = j & (NW8 - 1);
        src = (w == 0) ? wq : (w == 1) ? wk : (w == 2) ? wv : wo;
        dst = (w == 0) ? g_wq : (w == 1) ? g_wk : (w == 2) ? g_wv : g_wo;
    }
    float4 a = ((const float4*)src)[2 * idx];
    float4 b = ((const float4*)src)[2 * idx + 1];
    uint4 o;
    o.x = fpack2(a.x, a.y); o.y = fpack2(a.z, a.w);
    o.z = fpack2(b.x, b.y); o.w = fpack2(b.z, b.w);
    ((uint4*)dst)[idx] = o;
}

// ============================================================================
// fp16 GEMM body, cp.async double-buffered. C = A @ W^T + bias.
// BM=128 BN=128 BK=32, 256 threads, 8 warps (2Mx4N), warp tile 64x32.
// smem row stride 20 words (80 B): 16B-aligned for cp.async; (20g+q)%32 is a
// full bank permutation -> conflict-free fragment reads, no XOR needed.
// ============================================================================
struct GemmSmem {
    uint32_t Ab[2][128 * 20];
    uint32_t Wb[2][128 * 20];
};

__device__ __forceinline__ void gemm_body(
    const __half* __restrict__ A, const __half* __restrict__ W,
    const float* __restrict__ bias, __half* Chalf, float* Cfloat,
    GemmSmem& sm, int bm, int bn)
{
    const int tid = threadIdx.x;
    const int wid = tid >> 5;
    const int lane = tid & 31;
    const int g = lane >> 2;
    const int q = lane & 3;
    const int wm = (wid & 1) * 64;
    const int wn = (wid >> 1) * 32;

    const uint32_t smA[2] = { cvta_sh(sm.Ab[0]), cvta_sh(sm.Ab[1]) };
    const uint32_t smW[2] = { cvta_sh(sm.Wb[0]), cvta_sh(sm.Wb[1]) };

    auto stage = [&](int buf, int kb) {
#pragma unroll
        for (int i = 0; i < 2; i++) {
            int id = i * 256 + tid;
            int row = id >> 2;
            int c = id & 3;
            uint32_t doff = (uint32_t)(row * 80 + c * 16);
            cp16(smA[buf] + doff, A + (size_t)(bm + row) * HIDDEN + kb * 32 + c * 8);
            cp16(smW[buf] + doff, W + (size_t)(bn + row) * HIDDEN + kb * 32 + c * 8);
        }
    };

    float acc[4][4][4];
#pragma unroll
    for (int i = 0; i < 4; i++)
#pragma unroll
        for (int j = 0; j < 4; j++)
#pragma unroll
            for (int r = 0; r < 4; r++) acc[i][j][r] = 0.0f;

    stage(0, 0);
    cp_commit();

    for (int kb = 0; kb < 32; kb++) {
        const int cur = kb & 1;
        if (kb < 31) {
            stage(cur ^ 1, kb + 1);
            cp_commit();
            cp_wait1();
        } else {
            cp_wait0();
        }
        __syncthreads();

        const uint32_t* __restrict__ As = sm.Ab[cur];
        const uint32_t* __restrict__ Ws = sm.Wb[cur];

#pragma unroll
        for (int ks = 0; ks < 2; ks++) {
            const int kw = ks * 8;
            uint32_t af[4][4];
#pragma unroll
            for (int mt = 0; mt < 4; mt++) {
                int m0 = wm + mt * 16;
                af[mt][0] = As[(m0 + g) * 20 + kw + q];
                af[mt][1] = As[(m0 + 8 + g) * 20 + kw + q];
                af[mt][2] = As[(m0 + g) * 20 + kw + q + 4];
                af[mt][3] = As[(m0 + 8 + g) * 20 + kw + q + 4];
            }
            uint32_t bf[4][2];
#pragma unroll
            for (int nt = 0; nt < 4; nt++) {
                int n0 = wn + nt * 8;
                bf[nt][0] = Ws[(n0 + g) * 20 + kw + q];
                bf[nt][1] = Ws[(n0 + g) * 20 + kw + q + 4];
            }
#pragma unroll
            for (int mt = 0; mt < 4; mt++)
#pragma unroll
                for (int nt = 0; nt < 4; nt++)
                    mma_f16(acc[mt][nt], af[mt], bf[nt][0], bf[nt][1]);
        }
        __syncthreads();
    }

    // ---- epilogue ----
    if (Chalf) {
        uint32_t* C32 = (uint32_t*)Chalf;
#pragma unroll
        for (int nt = 0; nt < 4; nt++) {
            int col = bn + wn + nt * 8 + 2 * q;
            float2 bb = *(const float2*)&bias[col];
            int colw = col >> 1;
#pragma unroll
            for (int mt = 0; mt < 4; mt++) {
                int row0 = bm + wm + mt * 16 + g;
                C32[(size_t)row0 * 512 + colw] =
                    fpack2(acc[mt][nt][0] + bb.x, acc[mt][nt][1] + bb.y);
                C32[(size_t)(row0 + 8) * 512 + colw] =
                    fpack2(acc[mt][nt][2] + bb.x, acc[mt][nt][3] + bb.y);
            }
        }
    } else {
#pragma unroll
        for (int nt = 0; nt < 4; nt++) {
            int col = bn + wn + nt * 8 + 2 * q;
            float2 bb = *(const float2*)&bias[col];
#pragma unroll
            for (int mt = 0; mt < 4; mt++) {
                int row0 = bm + wm + mt * 16 + g;
                *(float2*)&Cfloat[(size_t)row0 * HIDDEN + col] =
                    make_float2(acc[mt][nt][0] + bb.x, acc[mt][nt][1] + bb.y);
                *(float2*)&Cfloat[(size_t)(row0 + 8) * HIDDEN + col] =
                    make_float2(acc[mt][nt][2] + bb.x, acc[mt][nt][3] + bb.y);
            }
        }
    }
}

// Q/K/V projections in one launch: grid (8, 32, 3), z selects W/bias/dst.
__global__ __launch_bounds__(256, 2)
void gemm_qkv_kernel(const float* __restrict__ bq, const float* __restrict__ bk,
                     const float* __restrict__ bv)
{
    __shared__ GemmSmem sm;
    const int z = blockIdx.z;
    const __half* W = (z == 0) ? g_wq : (z == 1) ? g_wk : g_wv;
    const float* bias = (z == 0) ? bq : (z == 1) ? bk : bv;
    __half* C = (z == 0) ? g_q : (z == 1) ? g_k : g_v;
    gemm_body(g_x, W, bias, C, nullptr, sm, blockIdx.y * 128, blockIdx.x * 128);
}

// Output projection: g_ctx @ wo^T + bo -> f32 out.
__global__ __launch_bounds__(256, 2)
void gemm_out_kernel(const float* __restrict__ bo, float* __restrict__ out)
{
    __shared__ GemmSmem sm;
    gemm_body(g_ctx, g_wo, bo, nullptr, out, sm, blockIdx.y * 128, blockIdx.x * 128);
}

// ============================================================================
// Flash attention (R11, unchanged): fp16 mma, cp.async double-buffered K/V,
// ldmatrix.x4.trans V fragments. Static smem ~41 KB.
// ============================================================================
__global__ __launch_bounds__(128)
void attn_h_kernel()
{
    __shared__ uint32_t Kw[2][64 * 32];
    __shared__ uint32_t Vw[2][64 * 32];
    __shared__ uint32_t Ps[64][36];

    const int b = blockIdx.z;
    const int h = blockIdx.y;
    const int qb = blockIdx.x * 64;
    const int tid = threadIdx.x;
    const int wid = tid >> 5;
    const int lane = tid & 31;
    const int g = lane >> 2;
    const int q = lane & 3;

    const __half* kb_g = g_k + ((size_t)b * SEQ) * HIDDEN + h * HDIM;
    const __half* vb_g = g_v + ((size_t)b * SEQ) * HIDDEN + h * HDIM;
    const uint32_t smK[2] = { cvta_sh(Kw[0]), cvta_sh(Kw[1]) };
    const uint32_t smV[2] = { cvta_sh(Vw[0]), cvta_sh(Vw[1]) };

    auto stage = [&](int buf, int ktbase) {
#pragma unroll
        for (int i = 0; i < 4; i++) {
            int id = i * 128 + tid;
            int row = id >> 3;
            int c = id & 7;
            uint32_t doff = (uint32_t)(row * 128 + ((c ^ (row & 7)) << 4));
            cp16(smK[buf] + doff, kb_g + (size_t)(ktbase + row) * HIDDEN + c * 8);
            cp16(smV[buf] + doff, vb_g + (size_t)(ktbase + row) * HIDDEN + c * 8);
        }
    };

    stage(0, 0);
    cp_commit();

    const int qrow0 = qb + wid * 16 + g;
    const uint32_t qs = fpack2(0.125f, 0.125f);
    uint32_t qf[4][4];
    {
        const uint32_t* qp0 = (const uint32_t*)g_q +
                              ((size_t)b * SEQ + qrow0) * 512 + h * 32;
        const uint32_t* qp1 = qp0 + 8 * 512;
#pragma unroll
        for (int t = 0; t < 4; t++) {
            qf[t][0] = hmul2u(qp0[8 * t + q], qs);
            qf[t][1] = hmul2u(qp1[8 * t + q], qs);
            qf[t][2] = hmul2u(qp0[8 * t + q + 4], qs);
            qf[t][3] = hmul2u(qp1[8 * t + q + 4], qs);
        }
    }

    float oacc[8][4];
#pragma unroll
    for (int u = 0; u < 8; u++)
#pragma unroll
        for (int r = 0; r < 4; r++) oacc[u][r] = 0.0f;
    float m0 = -1e30f, m1 = -1e30f, l0 = 0.0f, l1 = 0.0f;

    const int prow0 = wid * 16 + g;

    for (int it = 0; it < SEQ / 64; it++) {
        const int cur = it & 1;
        cp_wait0();
        __syncthreads();
        if (it + 1 < SEQ / 64) {
            stage(cur ^ 1, (it + 1) * 64);
            cp_commit();
        }

        const uint32_t* __restrict__ K = Kw[cur];

        float sacc[8][4];
#pragma unroll
        for (int u = 0; u < 8; u++) {
#pragma unroll
            for (int r = 0; r < 4; r++) sacc[u][r] = 0.0f;
            const uint32_t* kr = K + (8 * u + g) * 32;
#pragma unroll
            for (int t = 0; t < 4; t++) {
                uint32_t b0 = kr[4 * ((2 * t) ^ g) + q];
                uint32_t b1 = kr[4 * ((2 * t + 1) ^ g) + q];
                mma_f16(sacc[u], qf[t], b0, b1);
            }
        }

        float mt0 = -1e30f, mt1 = -1e30f;
#pragma unroll
        for (int u = 0; u < 8; u++) {
            mt0 = fmaxf(mt0, fmaxf(sacc[u][0], sacc[u][1]));
            mt1 = fmaxf(mt1, fmaxf(sacc[u][2], sacc[u][3]));
        }
        mt0 = fmaxf(mt0, __shfl_xor_sync(0xffffffff, mt0, 1));
        mt0 = fmaxf(mt0, __shfl_xor_sync(0xffffffff, mt0, 2));
        mt1 = fmaxf(mt1, __shfl_xor_sync(0xffffffff, mt1, 1));
        mt1 = fmaxf(mt1, __shfl_xor_sync(0xffffffff, mt1, 2));

        float m0n = fmaxf(m0, mt0);
        float m1n = fmaxf(m1, mt1);
        float f0 = __expf(m0 - m0n);
        float f1 = __expf(m1 - m1n);
        m0 = m0n; m1 = m1n;

        float lt0 = 0.0f, lt1 = 0.0f;
#pragma unroll
        for (int u = 0; u < 8; u++) {
            float p0 = __expf(sacc[u][0] - m0n);
            float p1 = __expf(sacc[u][1] - m0n);
            float p2 = __expf(sacc[u][2] - m1n);
            float p3 = __expf(sacc[u][3] - m1n);
            lt0 += p0 + p1;
            lt1 += p2 + p3;
            Ps[prow0][4 * u + q]     = fpack2(p0, p1);
            Ps[prow0 + 8][4 * u + q] = fpack2(p2, p3);
        }
        lt0 += __shfl_xor_sync(0xffffffff, lt0, 1);
        lt0 += __shfl_xor_sync(0xffffffff, lt0, 2);
        lt1 += __shfl_xor_sync(0xffffffff, lt1, 1);
        lt1 += __shfl_xor_sync(0xffffffff, lt1, 2);
        l0 = l0 * f0 + lt0;
        l1 = l1 * f1 + lt1;

#pragma unroll
        for (int u = 0; u < 8; u++) {
            oacc[u][0] *= f0; oacc[u][1] *= f0;
            oacc[u][2] *= f1; oacc[u][3] *= f1;
        }
        __syncwarp();

        const int mat = lane >> 3;
        const int mrow = lane & 7;
#pragma unroll
        for (int t = 0; t < 4; t++) {
            uint32_t af[4];
            af[0] = Ps[prow0][8 * t + q];
            af[1] = Ps[prow0 + 8][8 * t + q];
            af[2] = Ps[prow0][8 * t + q + 4];
            af[3] = Ps[prow0 + 8][8 * t + q + 4];
#pragma unroll
            for (int u2 = 0; u2 < 4; u2++) {
                int key = 16 * t + (mat & 1) * 8 + mrow;
                int cn  = 2 * u2 + (mat >> 1);
                uint32_t addr = smV[cur] + key * 128 + ((cn ^ (key & 7)) << 4);
                uint32_t b0, b1, b2, b3;
                ldm_x4_t(b0, b1, b2, b3, addr);
                mma_f16(oacc[2 * u2], af, b0, b1);
                mma_f16(oacc[2 * u2 + 1], af, b2, b3);
            }
        }
    }

    float inv0 = 1.0f / l0;
    float inv1 = 1.0f / l1;
    uint32_t* op0 = (uint32_t*)g_ctx + ((size_t)b * SEQ + qrow0) * 512 + h * 32;
    uint32_t* op1 = op0 + 8 * 512;
#pragma unroll
    for (int u = 0; u < 8; u++) {
        op0[4 * u + q] = fpack2(oacc[u][0] * inv0, oacc[u][1] * inv0);
        op1[4 * u + q] = fpack2(oacc[u][2] * inv1, oacc[u][3] * inv1);
    }
}

// ============================================================================
// launcher — 4 graph nodes total (R11 had 5 and passed the mem guard).
// ============================================================================
extern "C" void kernel_launch(void* const* d_in, const int* in_sizes, int n_in,
                              void* d_out, int out_size)
{
    (void)in_sizes; (void)n_in; (void)out_size;
    const float* x  = (const float*)d_in[0];
    const float* wq = (const float*)d_in[1];
    const float* bq = (const float*)d_in[2];
    const float* wk = (const float*)d_in[3];
    const float* bk = (const float*)d_in[4];
    const float* wv = (const float*)d_in[5];
    const float* bv = (const float*)d_in[6];
    const float* wo = (const float*)d_in[7];
    const float* bo = (const float*)d_in[8];
    float* out = (float*)d_out;

    prep_kernel<<<NPREP / 256, 256>>>(x, wq, wk, wv, wo);

    dim3 qkvgrid(HIDDEN / 128, MROWS / 128, 3);  // (8, 32, 3)
    gemm_qkv_kernel<<<qkvgrid, 256>>>(bq, bk, bv);

    dim3 agrid(SEQ / 64, NHEADS, BATCH);         // (32, 16, 2)
    attn_h_kernel<<<agrid, 128>>>();

    dim3 ogrid(HIDDEN / 128, MROWS / 128);       // (8, 32)
    gemm_out_kernel<<<ogrid, 256>>>(bo, out);
}

// round 14
// speedup vs baseline: 7.4636x; 1.0069x over previous
#include <cuda_runtime.h>
#include <cuda_fp16.h>
#include <cstddef>
#include <cstdint>
#include <cstring>

#define HIDDEN 1024
#define SEQ    2048
#define BATCH  2
#define NHEADS 16
#define HDIM   64
#define MROWS  (BATCH * SEQ)   // 4096

// ---------------- scratch (fp16) ----------------
__device__ __align__(256) __half g_x [MROWS * HIDDEN];
__device__ __align__(256) __half g_wq[HIDDEN * HIDDEN];
__device__ __align__(256) __half g_wk[HIDDEN * HIDDEN];
__device__ __align__(256) __half g_wv[HIDDEN * HIDDEN];
__device__ __align__(256) __half g_wo[HIDDEN * HIDDEN];
__device__ __align__(256) __half g_q[BATCH * SEQ * HIDDEN];
__device__ __align__(256) __half g_k[BATCH * SEQ * HIDDEN];
__device__ __align__(256) __half g_v[BATCH * SEQ * HIDDEN];
__device__ __align__(256) __half g_ctx[BATCH * SEQ * HIDDEN];

// ---------------- helpers ----------------
__device__ __forceinline__ uint32_t fpack2(float a, float b) {
    __half2 h = __floats2half2_rn(a, b);
    uint32_t u; memcpy(&u, &h, 4); return u;
}
__device__ __forceinline__ uint32_t hmul2u(uint32_t a, uint32_t s) {
    __half2 ha, hs; memcpy(&ha, &a, 4); memcpy(&hs, &s, 4);
    __half2 r = __hmul2(ha, hs);
    uint32_t u; memcpy(&u, &r, 4); return u;
}
__device__ __forceinline__ void mma_f16(float d[4], const uint32_t a[4],
                                        uint32_t b0, uint32_t b1) {
    asm("mma.sync.aligned.m16n8k16.row.col.f32.f16.f16.f32 "
        "{%0,%1,%2,%3}, {%4,%5,%6,%7}, {%8,%9}, {%0,%1,%2,%3};"
        : "+f"(d[0]), "+f"(d[1]), "+f"(d[2]), "+f"(d[3])
        : "r"(a[0]), "r"(a[1]), "r"(a[2]), "r"(a[3]), "r"(b0), "r"(b1));
}
__device__ __forceinline__ void ldm_x4(uint32_t& r0, uint32_t& r1,
                                       uint32_t& r2, uint32_t& r3, uint32_t addr) {
    asm volatile("ldmatrix.sync.aligned.m8n8.x4.shared.b16 {%0,%1,%2,%3}, [%4];"
                 : "=r"(r0), "=r"(r1), "=r"(r2), "=r"(r3) : "r"(addr));
}
__device__ __forceinline__ void ldm_x4_t(uint32_t& r0, uint32_t& r1,
                                         uint32_t& r2, uint32_t& r3, uint32_t addr) {
    asm volatile("ldmatrix.sync.aligned.m8n8.x4.trans.shared.b16 {%0,%1,%2,%3}, [%4];"
                 : "=r"(r0), "=r"(r1), "=r"(r2), "=r"(r3) : "r"(addr));
}
__device__ __forceinline__ void cp16(uint32_t dst, const void* src) {
    asm volatile("cp.async.cg.shared.global [%0], [%1], 16;" :: "r"(dst), "l"(src));
}
__device__ __forceinline__ void cp_commit() { asm volatile("cp.async.commit_group;"); }
__device__ __forceinline__ void cp_wait0()  { asm volatile("cp.async.wait_group 0;"); }
__device__ __forceinline__ void cp_wait1()  { asm volatile("cp.async.wait_group 1;"); }
__device__ __forceinline__ uint32_t cvta_sh(const void* p) {
    return (uint32_t)__cvta_generic_to_shared(p);
}

// ============================================================================
// Fused prep: x + 4 weights f32 -> f16 in one launch.
// ============================================================================
#define NX8 (MROWS * HIDDEN / 8)    // 524288
#define NW8 (HIDDEN * HIDDEN / 8)   // 131072
#define NPREP (NX8 + 4 * NW8)       // 1048576

__global__ __launch_bounds__(256)
void prep_kernel(const float* __restrict__ x,
                 const float* __restrict__ wq, const float* __restrict__ wk,
                 const float* __restrict__ wv, const float* __restrict__ wo)
{
    int i = blockIdx.x * blockDim.x + threadIdx.x;
    if (i >= NPREP) return;
    const float* src;
    __half* dst;
    int idx;
    if (i < NX8) {
        src = x; dst = g_x; idx = i;
    } else {
        int j = i - NX8;
        int w = j >> 17;
        idx = j & (NW8 - 1);
        src = (w == 0) ? wq : (w == 1) ? wk : (w == 2) ? wv : wo;
        dst = (w == 0) ? g_wq : (w == 1) ? g_wk : (w == 2) ? g_wv : g_wo;
    }
    float4 a = ((const float4*)src)[2 * idx];
    float4 b = ((const float4*)src)[2 * idx + 1];
    uint4 o;
    o.x = fpack2(a.x, a.y); o.y = fpack2(a.z, a.w);
    o.z = fpack2(b.x, b.y); o.w = fpack2(b.z, b.w);
    ((uint4*)dst)[idx] = o;
}

// ============================================================================
// fp16 GEMM, 3-stage cp.async pipeline, ONE barrier per K-chunk.
// BM=128 BN=128 BK=32, 256 threads, 8 warps (2Mx4N), warp tile 64x32.
// smem row stride 20 words (80 B): cp.async-aligned + full bank permutation.
// Stage s at dyn smem offset s*20480 (A) / +10240 (W). Total 60 KB dynamic.
// ============================================================================
#define GEMM_SMEM3 (3 * 2 * 10240)   // 61440

__device__ __forceinline__ void gemm_body(
    const __half* __restrict__ A, const __half* __restrict__ W,
    const float* __restrict__ bias, __half* Chalf, float* Cfloat,
    uint32_t* gsm, int bm, int bn)
{
    const int tid = threadIdx.x;
    const int wid = tid >> 5;
    const int lane = tid & 31;
    const int g = lane >> 2;
    const int q = lane & 3;
    const int wm = (wid & 1) * 64;
    const int wn = (wid >> 1) * 32;

    const uint32_t smbase = cvta_sh(gsm);

    auto stage = [&](int s, int kb) {
#pragma unroll
        for (int i = 0; i < 2; i++) {
            int id = i * 256 + tid;
            int row = id >> 2;
            int c = id & 3;
            uint32_t doff = (uint32_t)(s * 20480 + row * 80 + c * 16);
            cp16(smbase + doff, A + (size_t)(bm + row) * HIDDEN + kb * 32 + c * 8);
            cp16(smbase + doff + 10240, W + (size_t)(bn + row) * HIDDEN + kb * 32 + c * 8);
        }
    };

    float acc[4][4][4];
#pragma unroll
    for (int i = 0; i < 4; i++)
#pragma unroll
        for (int j = 0; j < 4; j++)
#pragma unroll
            for (int r = 0; r < 4; r++) acc[i][j][r] = 0.0f;

    stage(0, 0); cp_commit();
    stage(1, 1); cp_commit();

    int sidx = 0;
    for (int kb = 0; kb < 32; kb++) {
        if (kb == 31) cp_wait0(); else cp_wait1();
        __syncthreads();
        if (kb + 2 < 32) {
            int sn = sidx + 2; if (sn >= 3) sn -= 3;
            stage(sn, kb + 2);
            cp_commit();
        }

        const uint32_t* __restrict__ As = gsm + sidx * 5120;
        const uint32_t* __restrict__ Ws = As + 2560;

#pragma unroll
        for (int ks = 0; ks < 2; ks++) {
            const int kw = ks * 8;
            uint32_t af[4][4];
#pragma unroll
            for (int mt = 0; mt < 4; mt++) {
                int m0 = wm + mt * 16;
                af[mt][0] = As[(m0 + g) * 20 + kw + q];
                af[mt][1] = As[(m0 + 8 + g) * 20 + kw + q];
                af[mt][2] = As[(m0 + g) * 20 + kw + q + 4];
                af[mt][3] = As[(m0 + 8 + g) * 20 + kw + q + 4];
            }
            uint32_t bf[4][2];
#pragma unroll
            for (int nt = 0; nt < 4; nt++) {
                int n0 = wn + nt * 8;
                bf[nt][0] = Ws[(n0 + g) * 20 + kw + q];
                bf[nt][1] = Ws[(n0 + g) * 20 + kw + q + 4];
            }
#pragma unroll
            for (int mt = 0; mt < 4; mt++)
#pragma unroll
                for (int nt = 0; nt < 4; nt++)
                    mma_f16(acc[mt][nt], af[mt], bf[nt][0], bf[nt][1]);
        }
        if (++sidx == 3) sidx = 0;
    }

    // ---- epilogue ----
    if (Chalf) {
        uint32_t* C32 = (uint32_t*)Chalf;
#pragma unroll
        for (int nt = 0; nt < 4; nt++) {
            int col = bn + wn + nt * 8 + 2 * q;
            float2 bb = *(const float2*)&bias[col];
            int colw = col >> 1;
#pragma unroll
            for (int mt = 0; mt < 4; mt++) {
                int row0 = bm + wm + mt * 16 + g;
                C32[(size_t)row0 * 512 + colw] =
                    fpack2(acc[mt][nt][0] + bb.x, acc[mt][nt][1] + bb.y);
                C32[(size_t)(row0 + 8) * 512 + colw] =
                    fpack2(acc[mt][nt][2] + bb.x, acc[mt][nt][3] + bb.y);
            }
        }
    } else {
#pragma unroll
        for (int nt = 0; nt < 4; nt++) {
            int col = bn + wn + nt * 8 + 2 * q;
            float2 bb = *(const float2*)&bias[col];
#pragma unroll
            for (int mt = 0; mt < 4; mt++) {
                int row0 = bm + wm + mt * 16 + g;
                *(float2*)&Cfloat[(size_t)row0 * HIDDEN + col] =
                    make_float2(acc[mt][nt][0] + bb.x, acc[mt][nt][1] + bb.y);
                *(float2*)&Cfloat[(size_t)(row0 + 8) * HIDDEN + col] =
                    make_float2(acc[mt][nt][2] + bb.x, acc[mt][nt][3] + bb.y);
            }
        }
    }
}

__global__ __launch_bounds__(256, 2)
void gemm_qkv_kernel(const float* __restrict__ bq, const float* __restrict__ bk,
                     const float* __restrict__ bv)
{
    extern __shared__ uint32_t gsm[];
    const int z = blockIdx.z;
    const __half* W = (z == 0) ? g_wq : (z == 1) ? g_wk : g_wv;
    const float* bias = (z == 0) ? bq : (z == 1) ? bk : bv;
    __half* C = (z == 0) ? g_q : (z == 1) ? g_k : g_v;
    gemm_body(g_x, W, bias, C, nullptr, gsm, blockIdx.y * 128, blockIdx.x * 128);
}

__global__ __launch_bounds__(256, 2)
void gemm_out_kernel(const float* __restrict__ bo, float* __restrict__ out)
{
    extern __shared__ uint32_t gsm[];
    gemm_body(g_ctx, g_wo, bo, nullptr, out, gsm, blockIdx.y * 128, blockIdx.x * 128);
}

// ============================================================================
// Flash attention v3: fp16 mma, cp.async double-buffered K/V (32 KB static),
// K B-frags via ldmatrix.x4 (non-trans), P held ENTIRELY in registers
// (C-frag layout == A-frag layout for fp16 m16n8k16), V via ldmatrix.x4.trans.
// CTA: 128 threads (4 warps), Q tile 64, K/V tile 64. grid (SEQ/64,NHEADS,BATCH)
// ============================================================================
__global__ __launch_bounds__(128)
void attn_h_kernel()
{
    __shared__ uint32_t Kw[2][64 * 32];
    __shared__ uint32_t Vw[2][64 * 32];

    const int b = blockIdx.z;
    const int h = blockIdx.y;
    const int qb = blockIdx.x * 64;
    const int tid = threadIdx.x;
    const int wid = tid >> 5;
    const int lane = tid & 31;
    const int g = lane >> 2;
    const int q = lane & 3;

    const __half* kb_g = g_k + ((size_t)b * SEQ) * HIDDEN + h * HDIM;
    const __half* vb_g = g_v + ((size_t)b * SEQ) * HIDDEN + h * HDIM;
    const uint32_t smK[2] = { cvta_sh(Kw[0]), cvta_sh(Kw[1]) };
    const uint32_t smV[2] = { cvta_sh(Vw[0]), cvta_sh(Vw[1]) };

    auto stage = [&](int buf, int ktbase) {
#pragma unroll
        for (int i = 0; i < 4; i++) {
            int id = i * 128 + tid;
            int row = id >> 3;
            int c = id & 7;
            uint32_t doff = (uint32_t)(row * 128 + ((c ^ (row & 7)) << 4));
            cp16(smK[buf] + doff, kb_g + (size_t)(ktbase + row) * HIDDEN + c * 8);
            cp16(smV[buf] + doff, vb_g + (size_t)(ktbase + row) * HIDDEN + c * 8);
        }
    };

    stage(0, 0);
    cp_commit();

    // Q fragments (fp16), scaled by 1/8
    const int qrow0 = qb + wid * 16 + g;
    const uint32_t qs = fpack2(0.125f, 0.125f);
    uint32_t qf[4][4];
    {
        const uint32_t* qp0 = (const uint32_t*)g_q +
                              ((size_t)b * SEQ + qrow0) * 512 + h * 32;
        const uint32_t* qp1 = qp0 + 8 * 512;
#pragma unroll
        for (int t = 0; t < 4; t++) {
            qf[t][0] = hmul2u(qp0[8 * t + q], qs);
            qf[t][1] = hmul2u(qp1[8 * t + q], qs);
            qf[t][2] = hmul2u(qp0[8 * t + q + 4], qs);
            qf[t][3] = hmul2u(qp1[8 * t + q + 4], qs);
        }
    }

    float oacc[8][4];
#pragma unroll
    for (int u = 0; u < 8; u++)
#pragma unroll
        for (int r = 0; r < 4; r++) oacc[u][r] = 0.0f;
    float m0 = -1e30f, m1 = -1e30f, l0 = 0.0f, l1 = 0.0f;

    // ldmatrix lane mapping: lane = 8*j + l  (j = matrix, l = row)
    const int lj = lane >> 3;
    const int ll = lane & 7;

    for (int it = 0; it < SEQ / 64; it++) {
        const int cur = it & 1;
        cp_wait0();
        __syncthreads();
        if (it + 1 < SEQ / 64) {
            stage(cur ^ 1, (it + 1) * 64);
            cp_commit();
        }

        // ---- S = Q K^T  (K B-frags via non-trans ldmatrix.x4) ----
        float sacc[8][4];
#pragma unroll
        for (int u = 0; u < 8; u++) {
#pragma unroll
            for (int r = 0; r < 4; r++) sacc[u][r] = 0.0f;
            uint32_t rowa = smK[cur] + (uint32_t)((8 * u + ll) * 128);
            uint32_t k0, k1, k2, k3, k4, k5, k6, k7;
            ldm_x4(k0, k1, k2, k3, rowa + (uint32_t)(((lj)     ^ ll) << 4));
            ldm_x4(k4, k5, k6, k7, rowa + (uint32_t)(((4 + lj) ^ ll) << 4));
            mma_f16(sacc[u], qf[0], k0, k1);
            mma_f16(sacc[u], qf[1], k2, k3);
            mma_f16(sacc[u], qf[2], k4, k5);
            mma_f16(sacc[u], qf[3], k6, k7);
        }

        // ---- online softmax (P stays in registers as A-fragments) ----
        float mt0 = -1e30f, mt1 = -1e30f;
#pragma unroll
        for (int u = 0; u < 8; u++) {
            mt0 = fmaxf(mt0, fmaxf(sacc[u][0], sacc[u][1]));
            mt1 = fmaxf(mt1, fmaxf(sacc[u][2], sacc[u][3]));
        }
        mt0 = fmaxf(mt0, __shfl_xor_sync(0xffffffff, mt0, 1));
        mt0 = fmaxf(mt0, __shfl_xor_sync(0xffffffff, mt0, 2));
        mt1 = fmaxf(mt1, __shfl_xor_sync(0xffffffff, mt1, 1));
        mt1 = fmaxf(mt1, __shfl_xor_sync(0xffffffff, mt1, 2));

        float m0n = fmaxf(m0, mt0);
        float m1n = fmaxf(m1, mt1);
        float f0 = __expf(m0 - m0n);
        float f1 = __expf(m1 - m1n);
        m0 = m0n; m1 = m1n;

        uint32_t paf[4][4];
        float lt0 = 0.0f, lt1 = 0.0f;
#pragma unroll
        for (int u = 0; u < 8; u++) {
            float p0 = __expf(sacc[u][0] - m0n);
            float p1 = __expf(sacc[u][1] - m0n);
            float p2 = __expf(sacc[u][2] - m1n);
            float p3 = __expf(sacc[u][3] - m1n);
            lt0 += p0 + p1;
            lt1 += p2 + p3;
            int base = (u & 1) << 1;
            paf[u >> 1][base]     = fpack2(p0, p1);   // rows g
            paf[u >> 1][base + 1] = fpack2(p2, p3);   // rows g+8
        }
        lt0 += __shfl_xor_sync(0xffffffff, lt0, 1);
        lt0 += __shfl_xor_sync(0xffffffff, lt0, 2);
        lt1 += __shfl_xor_sync(0xffffffff, lt1, 1);
        lt1 += __shfl_xor_sync(0xffffffff, lt1, 2);
        l0 = l0 * f0 + lt0;
        l1 = l1 * f1 + lt1;

#pragma unroll
        for (int u = 0; u < 8; u++) {
            oacc[u][0] *= f0; oacc[u][1] *= f0;
            oacc[u][2] *= f1; oacc[u][3] *= f1;
        }

        // ---- O += P V  (V B-frags via ldmatrix.x4.trans; P from registers) ----
        const int mat = lane >> 3;
        const int mrow = lane & 7;
#pragma unroll
        for (int t = 0; t < 4; t++) {
            // A-frag order for k-block t: {rows g @ u=2t, rows g+8 @ u=2t,
            //                              rows g @ u=2t+1, rows g+8 @ u=2t+1}
            uint32_t af[4] = { paf[t][0], paf[t][1], paf[t][2], paf[t][3] };
#pragma unroll
            for (int u2 = 0; u2 < 4; u2++) {
                int key = 16 * t + (mat & 1) * 8 + mrow;
                int cn  = 2 * u2 + (mat >> 1);
                uint32_t addr = smV[cur] + key * 128 + ((cn ^ (key & 7)) << 4);
                uint32_t b0, b1, b2, b3;
                ldm_x4_t(b0, b1, b2, b3, addr);
                mma_f16(oacc[2 * u2], af, b0, b1);
                mma_f16(oacc[2 * u2 + 1], af, b2, b3);
            }
        }
    }

    // ---- write ctx as fp16 ----
    float inv0 = 1.0f / l0;
    float inv1 = 1.0f / l1;
    uint32_t* op0 = (uint32_t*)g_ctx + ((size_t)b * SEQ + qrow0) * 512 + h * 32;
    uint32_t* op1 = op0 + 8 * 512;
#pragma unroll
    for (int u = 0; u < 8; u++) {
        op0[4 * u + q] = fpack2(oacc[u][0] * inv0, oacc[u][1] * inv0);
        op1[4 * u + q] = fpack2(oacc[u][2] * inv1, oacc[u][3] * inv1);
    }
}

// ============================================================================
// launcher — 4 graph nodes.
// ============================================================================
extern "C" void kernel_launch(void* const* d_in, const int* in_sizes, int n_in,
                              void* d_out, int out_size)
{
    (void)in_sizes; (void)n_in; (void)out_size;
    const float* x  = (const float*)d_in[0];
    const float* wq = (const float*)d_in[1];
    const float* bq = (const float*)d_in[2];
    const float* wk = (const float*)d_in[3];
    const float* bk = (const float*)d_in[4];
    const float* wv = (const float*)d_in[5];
    const float* bv = (const float*)d_in[6];
    const float* wo = (const float*)d_in[7];
    const float* bo = (const float*)d_in[8];
    float* out = (float*)d_out;

    static bool attr_set = false;
    if (!attr_set) {
        cudaFuncSetAttribute(gemm_qkv_kernel,
                             cudaFuncAttributeMaxDynamicSharedMemorySize, GEMM_SMEM3);
        cudaFuncSetAttribute(gemm_out_kernel,
                             cudaFuncAttributeMaxDynamicSharedMemorySize, GEMM_SMEM3);
        attr_set = true;
    }

    prep_kernel<<<NPREP / 256, 256>>>(x, wq, wk, wv, wo);

    dim3 qkvgrid(HIDDEN / 128, MROWS / 128, 3);
    gemm_qkv_kernel<<<qkvgrid, 256, GEMM_SMEM3>>>(bq, bk, bv);

    dim3 agrid(SEQ / 64, NHEADS, BATCH);
    attn_h_kernel<<<agrid, 128>>>();

    dim3 ogrid(HIDDEN / 128, MROWS / 128);
    gemm_out_kernel<<<ogrid, 256, GEMM_SMEM3>>>(bo, out);
}

// round 15
// speedup vs baseline: 8.1297x; 1.0892x over previous
#include <cuda_runtime.h>
#include <cuda_fp16.h>
#include <cstddef>
#include <cstdint>
#include <cstring>

#define HIDDEN 1024
#define SEQ    2048
#define BATCH  2
#define NHEADS 16
#define HDIM   64
#define MROWS  (BATCH * SEQ)   // 4096

// ---------------- scratch (fp16) ----------------
__device__ __align__(256) __half g_x [MROWS * HIDDEN];
__device__ __align__(256) __half g_wq[HIDDEN * HIDDEN];
__device__ __align__(256) __half g_wk[HIDDEN * HIDDEN];
__device__ __align__(256) __half g_wv[HIDDEN * HIDDEN];
__device__ __align__(256) __half g_wo[HIDDEN * HIDDEN];
__device__ __align__(256) __half g_q[BATCH * SEQ * HIDDEN];
__device__ __align__(256) __half g_k[BATCH * SEQ * HIDDEN];
__device__ __align__(256) __half g_v[BATCH * SEQ * HIDDEN];
__device__ __align__(256) __half g_ctx[BATCH * SEQ * HIDDEN];

// ---------------- helpers ----------------
__device__ __forceinline__ uint32_t fpack2(float a, float b) {
    __half2 h = __floats2half2_rn(a, b);
    uint32_t u; memcpy(&u, &h, 4); return u;
}
__device__ __forceinline__ uint32_t hmul2u(uint32_t a, uint32_t s) {
    __half2 ha, hs; memcpy(&ha, &a, 4); memcpy(&hs, &s, 4);
    __half2 r = __hmul2(ha, hs);
    uint32_t u; memcpy(&u, &r, 4); return u;
}
__device__ __forceinline__ float ex2f(float x) {
    float y; asm("ex2.approx.f32 %0, %1;" : "=f"(y) : "f"(x)); return y;
}
__device__ __forceinline__ void mma_f16(float d[4], const uint32_t a[4],
                                        uint32_t b0, uint32_t b1) {
    asm("mma.sync.aligned.m16n8k16.row.col.f32.f16.f16.f32 "
        "{%0,%1,%2,%3}, {%4,%5,%6,%7}, {%8,%9}, {%0,%1,%2,%3};"
        : "+f"(d[0]), "+f"(d[1]), "+f"(d[2]), "+f"(d[3])
        : "r"(a[0]), "r"(a[1]), "r"(a[2]), "r"(a[3]), "r"(b0), "r"(b1));
}
__device__ __forceinline__ void ldm_x4(uint32_t& r0, uint32_t& r1,
                                       uint32_t& r2, uint32_t& r3, uint32_t addr) {
    asm volatile("ldmatrix.sync.aligned.m8n8.x4.shared.b16 {%0,%1,%2,%3}, [%4];"
                 : "=r"(r0), "=r"(r1), "=r"(r2), "=r"(r3) : "r"(addr));
}
__device__ __forceinline__ void ldm_x4_t(uint32_t& r0, uint32_t& r1,
                                         uint32_t& r2, uint32_t& r3, uint32_t addr) {
    asm volatile("ldmatrix.sync.aligned.m8n8.x4.trans.shared.b16 {%0,%1,%2,%3}, [%4];"
                 : "=r"(r0), "=r"(r1), "=r"(r2), "=r"(r3) : "r"(addr));
}
__device__ __forceinline__ void cp16(uint32_t dst, const void* src) {
    asm volatile("cp.async.cg.shared.global [%0], [%1], 16;" :: "r"(dst), "l"(src));
}
__device__ __forceinline__ void cp_commit() { asm volatile("cp.async.commit_group;"); }
__device__ __forceinline__ void cp_wait0()  { asm volatile("cp.async.wait_group 0;"); }
__device__ __forceinline__ void cp_wait1()  { asm volatile("cp.async.wait_group 1;"); }
__device__ __forceinline__ uint32_t cvta_sh(const void* p) {
    return (uint32_t)__cvta_generic_to_shared(p);
}

// ============================================================================
// Fused prep: x + 4 weights f32 -> f16 in one launch.
// ============================================================================
#define NX8 (MROWS * HIDDEN / 8)    // 524288
#define NW8 (HIDDEN * HIDDEN / 8)   // 131072
#define NPREP (NX8 + 4 * NW8)       // 1048576

__global__ __launch_bounds__(256)
void prep_kernel(const float* __restrict__ x,
                 const float* __restrict__ wq, const float* __restrict__ wk,
                 const float* __restrict__ wv, const float* __restrict__ wo)
{
    int i = blockIdx.x * blockDim.x + threadIdx.x;
    if (i >= NPREP) return;
    const float* src;
    __half* dst;
    int idx;
    if (i < NX8) {
        src = x; dst = g_x; idx = i;
    } else {
        int j = i - NX8;
        int w = j >> 17;
        idx = j & (NW8 - 1);
        src = (w == 0) ? wq : (w == 1) ? wk : (w == 2) ? wv : wo;
        dst = (w == 0) ? g_wq : (w == 1) ? g_wk : (w == 2) ? g_wv : g_wo;
    }
    float4 a = ((const float4*)src)[2 * idx];
    float4 b = ((const float4*)src)[2 * idx + 1];
    uint4 o;
    o.x = fpack2(a.x, a.y); o.y = fpack2(a.z, a.w);
    o.z = fpack2(b.x, b.y); o.w = fpack2(b.z, b.w);
    ((uint4*)dst)[idx] = o;
}

// ============================================================================
// fp16 GEMM, 3-stage cp.async pipeline, fragments via ldmatrix.x4.
// BM=128 BN=128 BK=32, 256 threads, 8 warps (2Mx4N), warp tile 64x32.
// smem row stride 20 words (80 B): cp.async-aligned; 8-row ldmatrix groups hit
// disjoint bank spans (20r mod 32 = {0,20,8,28,16,4,24,12}) -> conflict-free.
// ============================================================================
#define GEMM_SMEM3 (3 * 2 * 10240)   // 61440

__device__ __forceinline__ void gemm_body(
    const __half* __restrict__ A, const __half* __restrict__ W,
    const float* __restrict__ bias, __half* Chalf, float* Cfloat,
    uint32_t* gsm, int bm, int bn)
{
    const int tid = threadIdx.x;
    const int wid = tid >> 5;
    const int lane = tid & 31;
    const int g = lane >> 2;
    const int q = lane & 3;
    const int wm = (wid & 1) * 64;
    const int wn = (wid >> 1) * 32;

    const uint32_t smbase = cvta_sh(gsm);

    auto stage = [&](int s, int kb) {
#pragma unroll
        for (int i = 0; i < 2; i++) {
            int id = i * 256 + tid;
            int row = id >> 2;
            int c = id & 3;
            uint32_t doff = (uint32_t)(s * 20480 + row * 80 + c * 16);
            cp16(smbase + doff, A + (size_t)(bm + row) * HIDDEN + kb * 32 + c * 8);
            cp16(smbase + doff + 10240, W + (size_t)(bn + row) * HIDDEN + kb * 32 + c * 8);
        }
    };

    float acc[4][4][4];
#pragma unroll
    for (int i = 0; i < 4; i++)
#pragma unroll
        for (int j = 0; j < 4; j++)
#pragma unroll
            for (int r = 0; r < 4; r++) acc[i][j][r] = 0.0f;

    stage(0, 0); cp_commit();
    stage(1, 1); cp_commit();

    // ldmatrix lane-address components (constant across chunks)
    const int l16 = lane & 15;               // A: row within 16
    const int ahalf = (lane >> 4) << 4;      // A: +16B for k-hi half
    const int l8 = lane & 7;                 // B: row within 8
    const int bgrp = lane >> 3;              // B: 0..3
    const int brow = (bgrp >> 1) * 8 + l8;   // B: row offset within 16-n group
    const int bkoff = (bgrp & 1) << 4;       // B: k-half byte offset

    int sidx = 0;
    for (int kb = 0; kb < 32; kb++) {
        if (kb == 31) cp_wait0(); else cp_wait1();
        __syncthreads();
        if (kb + 2 < 32) {
            int sn = sidx + 2; if (sn >= 3) sn -= 3;
            stage(sn, kb + 2);
            cp_commit();
        }

        const uint32_t As_b = smbase + (uint32_t)(sidx * 20480);
        const uint32_t Ws_b = As_b + 10240;

#pragma unroll
        for (int ks = 0; ks < 2; ks++) {
            const uint32_t koff = (uint32_t)(ks * 32);   // 8 words = 32 B
            uint32_t af[4][4];
#pragma unroll
            for (int mt = 0; mt < 4; mt++) {
                uint32_t aaddr = As_b + (uint32_t)((wm + mt * 16 + l16) * 80) + koff + ahalf;
                ldm_x4(af[mt][0], af[mt][1], af[mt][2], af[mt][3], aaddr);
            }
            uint32_t bf[4][2];
            {
                uint32_t baddr0 = Ws_b + (uint32_t)((wn + brow) * 80) + koff + bkoff;
                uint32_t baddr1 = Ws_b + (uint32_t)((wn + 16 + brow) * 80) + koff + bkoff;
                ldm_x4(bf[0][0], bf[0][1], bf[1][0], bf[1][1], baddr0);
                ldm_x4(bf[2][0], bf[2][1], bf[3][0], bf[3][1], baddr1);
            }
#pragma unroll
            for (int mt = 0; mt < 4; mt++)
#pragma unroll
                for (int nt = 0; nt < 4; nt++)
                    mma_f16(acc[mt][nt], af[mt], bf[nt][0], bf[nt][1]);
        }
        if (++sidx == 3) sidx = 0;
    }

    // ---- epilogue ----
    if (Chalf) {
        uint32_t* C32 = (uint32_t*)Chalf;
#pragma unroll
        for (int nt = 0; nt < 4; nt++) {
            int col = bn + wn + nt * 8 + 2 * q;
            float2 bb = *(const float2*)&bias[col];
            int colw = col >> 1;
#pragma unroll
            for (int mt = 0; mt < 4; mt++) {
                int row0 = bm + wm + mt * 16 + g;
                C32[(size_t)row0 * 512 + colw] =
                    fpack2(acc[mt][nt][0] + bb.x, acc[mt][nt][1] + bb.y);
                C32[(size_t)(row0 + 8) * 512 + colw] =
                    fpack2(acc[mt][nt][2] + bb.x, acc[mt][nt][3] + bb.y);
            }
        }
    } else {
#pragma unroll
        for (int nt = 0; nt < 4; nt++) {
            int col = bn + wn + nt * 8 + 2 * q;
            float2 bb = *(const float2*)&bias[col];
#pragma unroll
            for (int mt = 0; mt < 4; mt++) {
                int row0 = bm + wm + mt * 16 + g;
                *(float2*)&Cfloat[(size_t)row0 * HIDDEN + col] =
                    make_float2(acc[mt][nt][0] + bb.x, acc[mt][nt][1] + bb.y);
                *(float2*)&Cfloat[(size_t)(row0 + 8) * HIDDEN + col] =
                    make_float2(acc[mt][nt][2] + bb.x, acc[mt][nt][3] + bb.y);
            }
        }
    }
}

__global__ __launch_bounds__(256, 2)
void gemm_qkv_kernel(const float* __restrict__ bq, const float* __restrict__ bk,
                     const float* __restrict__ bv)
{
    extern __shared__ uint32_t gsm[];
    const int z = blockIdx.z;
    const __half* W = (z == 0) ? g_wq : (z == 1) ? g_wk : g_wv;
    const float* bias = (z == 0) ? bq : (z == 1) ? bk : bv;
    __half* C = (z == 0) ? g_q : (z == 1) ? g_k : g_v;
    gemm_body(g_x, W, bias, C, nullptr, gsm, blockIdx.y * 128, blockIdx.x * 128);
}

__global__ __launch_bounds__(256, 2)
void gemm_out_kernel(const float* __restrict__ bo, float* __restrict__ out)
{
    extern __shared__ uint32_t gsm[];
    gemm_body(g_ctx, g_wo, bo, nullptr, out, gsm, blockIdx.y * 128, blockIdx.x * 128);
}

// ============================================================================
// Flash attention v4: fp16 mma, cp.async double-buffered K/V (32 KB static),
// ldmatrix for K and V fragments, P register-resident, softmax in log2-domain
// (Q pre-scaled by 0.125*log2e; exp = single ex2.approx).
// CTA: 128 threads (4 warps), Q tile 64, K/V tile 64. grid (SEQ/64,NHEADS,BATCH)
// ============================================================================
__global__ __launch_bounds__(128)
void attn_h_kernel()
{
    __shared__ uint32_t Kw[2][64 * 32];
    __shared__ uint32_t Vw[2][64 * 32];

    const int b = blockIdx.z;
    const int h = blockIdx.y;
    const int qb = blockIdx.x * 64;
    const int tid = threadIdx.x;
    const int wid = tid >> 5;
    const int lane = tid & 31;
    const int g = lane >> 2;
    const int q = lane & 3;

    const __half* kb_g = g_k + ((size_t)b * SEQ) * HIDDEN + h * HDIM;
    const __half* vb_g = g_v + ((size_t)b * SEQ) * HIDDEN + h * HDIM;
    const uint32_t smK[2] = { cvta_sh(Kw[0]), cvta_sh(Kw[1]) };
    const uint32_t smV[2] = { cvta_sh(Vw[0]), cvta_sh(Vw[1]) };

    auto stage = [&](int buf, int ktbase) {
#pragma unroll
        for (int i = 0; i < 4; i++) {
            int id = i * 128 + tid;
            int row = id >> 3;
            int c = id & 7;
            uint32_t doff = (uint32_t)(row * 128 + ((c ^ (row & 7)) << 4));
            cp16(smK[buf] + doff, kb_g + (size_t)(ktbase + row) * HIDDEN + c * 8);
            cp16(smV[buf] + doff, vb_g + (size_t)(ktbase + row) * HIDDEN + c * 8);
        }
    };

    stage(0, 0);
    cp_commit();

    // Q fragments scaled by 0.125 * log2(e) -> scores come out in log2 units
    const int qrow0 = qb + wid * 16 + g;
    const float QS = 0.18033688f;   // 0.125 * 1.4426950408889634
    const uint32_t qs = fpack2(QS, QS);
    uint32_t qf[4][4];
    {
        const uint32_t* qp0 = (const uint32_t*)g_q +
                              ((size_t)b * SEQ + qrow0) * 512 + h * 32;
        const uint32_t* qp1 = qp0 + 8 * 512;
#pragma unroll
        for (int t = 0; t < 4; t++) {
            qf[t][0] = hmul2u(qp0[8 * t + q], qs);
            qf[t][1] = hmul2u(qp1[8 * t + q], qs);
            qf[t][2] = hmul2u(qp0[8 * t + q + 4], qs);
            qf[t][3] = hmul2u(qp1[8 * t + q + 4], qs);
        }
    }

    float oacc[8][4];
#pragma unroll
    for (int u = 0; u < 8; u++)
#pragma unroll
        for (int r = 0; r < 4; r++) oacc[u][r] = 0.0f;
    float m0 = -1e30f, m1 = -1e30f, l0 = 0.0f, l1 = 0.0f;

    const int lj = lane >> 3;
    const int ll = lane & 7;

    for (int it = 0; it < SEQ / 64; it++) {
        const int cur = it & 1;
        cp_wait0();
        __syncthreads();
        if (it + 1 < SEQ / 64) {
            stage(cur ^ 1, (it + 1) * 64);
            cp_commit();
        }

        // ---- S = Q K^T  (log2-domain scores) ----
        float sacc[8][4];
#pragma unroll
        for (int u = 0; u < 8; u++) {
#pragma unroll
            for (int r = 0; r < 4; r++) sacc[u][r] = 0.0f;
            uint32_t rowa = smK[cur] + (uint32_t)((8 * u + ll) * 128);
            uint32_t k0, k1, k2, k3, k4, k5, k6, k7;
            ldm_x4(k0, k1, k2, k3, rowa + (uint32_t)(((lj)     ^ ll) << 4));
            ldm_x4(k4, k5, k6, k7, rowa + (uint32_t)(((4 + lj) ^ ll) << 4));
            mma_f16(sacc[u], qf[0], k0, k1);
            mma_f16(sacc[u], qf[1], k2, k3);
            mma_f16(sacc[u], qf[2], k4, k5);
            mma_f16(sacc[u], qf[3], k6, k7);
        }

        // ---- online softmax (base-2) ----
        float mt0 = -1e30f, mt1 = -1e30f;
#pragma unroll
        for (int u = 0; u < 8; u++) {
            mt0 = fmaxf(mt0, fmaxf(sacc[u][0], sacc[u][1]));
            mt1 = fmaxf(mt1, fmaxf(sacc[u][2], sacc[u][3]));
        }
        mt0 = fmaxf(mt0, __shfl_xor_sync(0xffffffff, mt0, 1));
        mt0 = fmaxf(mt0, __shfl_xor_sync(0xffffffff, mt0, 2));
        mt1 = fmaxf(mt1, __shfl_xor_sync(0xffffffff, mt1, 1));
        mt1 = fmaxf(mt1, __shfl_xor_sync(0xffffffff, mt1, 2));

        float m0n = fmaxf(m0, mt0);
        float m1n = fmaxf(m1, mt1);
        float f0 = ex2f(m0 - m0n);
        float f1 = ex2f(m1 - m1n);
        m0 = m0n; m1 = m1n;

        uint32_t paf[4][4];
        float lt0 = 0.0f, lt1 = 0.0f;
#pragma unroll
        for (int u = 0; u < 8; u++) {
            float p0 = ex2f(sacc[u][0] - m0n);
            float p1 = ex2f(sacc[u][1] - m0n);
            float p2 = ex2f(sacc[u][2] - m1n);
            float p3 = ex2f(sacc[u][3] - m1n);
            lt0 += p0 + p1;
            lt1 += p2 + p3;
            int base = (u & 1) << 1;
            paf[u >> 1][base]     = fpack2(p0, p1);
            paf[u >> 1][base + 1] = fpack2(p2, p3);
        }
        lt0 += __shfl_xor_sync(0xffffffff, lt0, 1);
        lt0 += __shfl_xor_sync(0xffffffff, lt0, 2);
        lt1 += __shfl_xor_sync(0xffffffff, lt1, 1);
        lt1 += __shfl_xor_sync(0xffffffff, lt1, 2);
        l0 = l0 * f0 + lt0;
        l1 = l1 * f1 + lt1;

#pragma unroll
        for (int u = 0; u < 8; u++) {
            oacc[u][0] *= f0; oacc[u][1] *= f0;
            oacc[u][2] *= f1; oacc[u][3] *= f1;
        }

        // ---- O += P V ----
        const int mat = lane >> 3;
        const int mrow = lane & 7;
#pragma unroll
        for (int t = 0; t < 4; t++) {
            uint32_t af[4] = { paf[t][0], paf[t][1], paf[t][2], paf[t][3] };
#pragma unroll
            for (int u2 = 0; u2 < 4; u2++) {
                int key = 16 * t + (mat & 1) * 8 + mrow;
                int cn  = 2 * u2 + (mat >> 1);
                uint32_t addr = smV[cur] + key * 128 + ((cn ^ (key & 7)) << 4);
                uint32_t b0, b1, b2, b3;
                ldm_x4_t(b0, b1, b2, b3, addr);
                mma_f16(oacc[2 * u2], af, b0, b1);
                mma_f16(oacc[2 * u2 + 1], af, b2, b3);
            }
        }
    }

    // ---- write ctx as fp16 ----
    float inv0 = 1.0f / l0;
    float inv1 = 1.0f / l1;
    uint32_t* op0 = (uint32_t*)g_ctx + ((size_t)b * SEQ + qrow0) * 512 + h * 32;
    uint32_t* op1 = op0 + 8 * 512;
#pragma unroll
    for (int u = 0; u < 8; u++) {
        op0[4 * u + q] = fpack2(oacc[u][0] * inv0, oacc[u][1] * inv0);
        op1[4 * u + q] = fpack2(oacc[u][2] * inv1, oacc[u][3] * inv1);
    }
}

// ============================================================================
// launcher — 4 graph nodes.
// ============================================================================
extern "C" void kernel_launch(void* const* d_in, const int* in_sizes, int n_in,
                              void* d_out, int out_size)
{
    (void)in_sizes; (void)n_in; (void)out_size;
    const float* x  = (const float*)d_in[0];
    const float* wq = (const float*)d_in[1];
    const float* bq = (const float*)d_in[2];
    const float* wk = (const float*)d_in[3];
    const float* bk = (const float*)d_in[4];
    const float* wv = (const float*)d_in[5];
    const float* bv = (const float*)d_in[6];
    const float* wo = (const float*)d_in[7];
    const float* bo = (const float*)d_in[8];
    float* out = (float*)d_out;

    static bool attr_set = false;
    if (!attr_set) {
        cudaFuncSetAttribute(gemm_qkv_kernel,
                             cudaFuncAttributeMaxDynamicSharedMemorySize, GEMM_SMEM3);
        cudaFuncSetAttribute(gemm_out_kernel,
                             cudaFuncAttributeMaxDynamicSharedMemorySize, GEMM_SMEM3);
        attr_set = true;
    }

    prep_kernel<<<NPREP / 256, 256>>>(x, wq, wk, wv, wo);

    dim3 qkvgrid(HIDDEN / 128, MROWS / 128, 3);
    gemm_qkv_kernel<<<qkvgrid, 256, GEMM_SMEM3>>>(bq, bk, bv);

    dim3 agrid(SEQ / 64, NHEADS, BATCH);
    attn_h_kernel<<<agrid, 128>>>();

    dim3 ogrid(HIDDEN / 128, MROWS / 128);
    gemm_out_kernel<<<ogrid, 256, GEMM_SMEM3>>>(bo, out);
}

// round 17
// speedup vs baseline: 8.7909x; 1.0813x over previous
#include <cuda_runtime.h>
#include <cuda_fp16.h>
#include <cstddef>
#include <cstdint>
#include <cstring>

#define HIDDEN 1024
#define SEQ    2048
#define BATCH  2
#define NHEADS 16
#define HDIM   64
#define MROWS  (BATCH * SEQ)   // 4096

// ---------------- scratch (fp16) ----------------
__device__ __align__(256) __half g_x [MROWS * HIDDEN];
__device__ __align__(256) __half g_wq[HIDDEN * HIDDEN];
__device__ __align__(256) __half g_wk[HIDDEN * HIDDEN];
__device__ __align__(256) __half g_wv[HIDDEN * HIDDEN];
__device__ __align__(256) __half g_wo[HIDDEN * HIDDEN];
__device__ __align__(256) __half g_q[BATCH * SEQ * HIDDEN];
__device__ __align__(256) __half g_k[BATCH * SEQ * HIDDEN];
__device__ __align__(256) __half g_v[BATCH * SEQ * HIDDEN];
__device__ __align__(256) __half g_ctx[BATCH * SEQ * HIDDEN];

// ---------------- helpers ----------------
__device__ __forceinline__ uint32_t fpack2(float a, float b) {
    __half2 h = __floats2half2_rn(a, b);
    uint32_t u; memcpy(&u, &h, 4); return u;
}
__device__ __forceinline__ uint32_t hmul2u(uint32_t a, uint32_t s) {
    __half2 ha, hs; memcpy(&ha, &a, 4); memcpy(&hs, &s, 4);
    __half2 r = __hmul2(ha, hs);
    uint32_t u; memcpy(&u, &r, 4); return u;
}
__device__ __forceinline__ float ex2f(float x) {
    float y; asm("ex2.approx.f32 %0, %1;" : "=f"(y) : "f"(x)); return y;
}
__device__ __forceinline__ uint32_t ex2h2(uint32_t x) {
    uint32_t y; asm("ex2.approx.f16x2 %0, %1;" : "=r"(y) : "r"(x)); return y;
}
__device__ __forceinline__ void mma_f16(float d[4], const uint32_t a[4],
                                        uint32_t b0, uint32_t b1) {
    asm("mma.sync.aligned.m16n8k16.row.col.f32.f16.f16.f32 "
        "{%0,%1,%2,%3}, {%4,%5,%6,%7}, {%8,%9}, {%0,%1,%2,%3};"
        : "+f"(d[0]), "+f"(d[1]), "+f"(d[2]), "+f"(d[3])
        : "r"(a[0]), "r"(a[1]), "r"(a[2]), "r"(a[3]), "r"(b0), "r"(b1));
}
__device__ __forceinline__ void ldm_x4(uint32_t& r0, uint32_t& r1,
                                       uint32_t& r2, uint32_t& r3, uint32_t addr) {
    asm volatile("ldmatrix.sync.aligned.m8n8.x4.shared.b16 {%0,%1,%2,%3}, [%4];"
                 : "=r"(r0), "=r"(r1), "=r"(r2), "=r"(r3) : "r"(addr));
}
__device__ __forceinline__ void ldm_x4_t(uint32_t& r0, uint32_t& r1,
                                         uint32_t& r2, uint32_t& r3, uint32_t addr) {
    asm volatile("ldmatrix.sync.aligned.m8n8.x4.trans.shared.b16 {%0,%1,%2,%3}, [%4];"
                 : "=r"(r0), "=r"(r1), "=r"(r2), "=r"(r3) : "r"(addr));
}
__device__ __forceinline__ void cp16(uint32_t dst, const void* src) {
    asm volatile("cp.async.cg.shared.global [%0], [%1], 16;" :: "r"(dst), "l"(src));
}
__device__ __forceinline__ void cp_commit() { asm volatile("cp.async.commit_group;"); }
__device__ __forceinline__ void cp_wait0()  { asm volatile("cp.async.wait_group 0;"); }
__device__ __forceinline__ void cp_wait1()  { asm volatile("cp.async.wait_group 1;"); }
__device__ __forceinline__ uint32_t cvta_sh(const void* p) {
    return (uint32_t)__cvta_generic_to_shared(p);
}

// ============================================================================
// Fused prep: x + 4 weights f32 -> f16 in one launch.
// ============================================================================
#define NX8 (MROWS * HIDDEN / 8)    // 524288
#define NW8 (HIDDEN * HIDDEN / 8)   // 131072
#define NPREP (NX8 + 4 * NW8)       // 1048576

__global__ __launch_bounds__(256)
void prep_kernel(const float* __restrict__ x,
                 const float* __restrict__ wq, const float* __restrict__ wk,
                 const float* __restrict__ wv, const float* __restrict__ wo)
{
    int i = blockIdx.x * blockDim.x + threadIdx.x;
    if (i >= NPREP) return;
    const float* src;
    __half* dst;
    int idx;
    if (i < NX8) {
        src = x; dst = g_x; idx = i;
    } else {
        int j = i - NX8;
        int w = j >> 17;
        idx = j & (NW8 - 1);
        src = (w == 0) ? wq : (w == 1) ? wk : (w == 2) ? wv : wo;
        dst = (w == 0) ? g_wq : (w == 1) ? g_wk : (w == 2) ? g_wv : g_wo;
    }
    float4 a = ((const float4*)src)[2 * idx];
    float4 b = ((const float4*)src)[2 * idx + 1];
    uint4 o;
    o.x = fpack2(a.x, a.y); o.y = fpack2(a.z, a.w);
    o.z = fpack2(b.x, b.y); o.w = fpack2(b.z, b.w);
    ((uint4*)dst)[idx] = o;
}

// ============================================================================
// fp16 GEMM, BK=64, 3-stage cp.async pipeline, ldmatrix fragments.
// BM=128 BN=128, 256 threads, 8 warps (2Mx4N), warp tile 64x32, 16 barriers.
// smem row stride 36 words (144 B): cp.async-aligned; ldmatrix 8-row groups at
// 36r mod 32 = 4r mod 32 -> all-distinct banks, conflict-free.
// Stage s: A at s*36864, W at +18432. Total 108 KB dynamic.
// ============================================================================
#define GEMM_STAGE_B 36864
#define GEMM_SMEM3 (3 * GEMM_STAGE_B)   // 110592

__device__ __forceinline__ void gemm_body(
    const __half* __restrict__ A, const __half* __restrict__ W,
    const float* __restrict__ bias, __half* Chalf, float* Cfloat,
    uint32_t* gsm, int bm, int bn)
{
    const int tid = threadIdx.x;
    const int wid = tid >> 5;
    const int lane = tid & 31;
    const int g = lane >> 2;
    const int q = lane & 3;
    const int wm = (wid & 1) * 64;
    const int wn = (wid >> 1) * 32;

    const uint32_t smbase = cvta_sh(gsm);

    auto stage = [&](int s, int kb) {
#pragma unroll
        for (int i = 0; i < 4; i++) {
            int id = i * 256 + tid;       // 0..1023
            int row = id >> 3;            // 0..127
            int c = id & 7;               // chunk 0..7 (16B each)
            uint32_t doff = (uint32_t)(s * GEMM_STAGE_B + row * 144 + c * 16);
            cp16(smbase + doff, A + (size_t)(bm + row) * HIDDEN + kb * 64 + c * 8);
            cp16(smbase + doff + 18432, W + (size_t)(bn + row) * HIDDEN + kb * 64 + c * 8);
        }
    };

    float acc[4][4][4];
#pragma unroll
    for (int i = 0; i < 4; i++)
#pragma unroll
        for (int j = 0; j < 4; j++)
#pragma unroll
            for (int r = 0; r < 4; r++) acc[i][j][r] = 0.0f;

    stage(0, 0); cp_commit();
    stage(1, 1); cp_commit();

    const int l16 = lane & 15;
    const int ahalf = (lane >> 4) << 4;
    const int l8 = lane & 7;
    const int bgrp = lane >> 3;
    const int brow = (bgrp >> 1) * 8 + l8;
    const int bkoff = (bgrp & 1) << 4;

    int sidx = 0;
    for (int kb = 0; kb < 16; kb++) {
        if (kb == 15) cp_wait0(); else cp_wait1();
        __syncthreads();
        if (kb + 2 < 16) {
            int sn = sidx + 2; if (sn >= 3) sn -= 3;
            stage(sn, kb + 2);
            cp_commit();
        }

        const uint32_t As_b = smbase + (uint32_t)(sidx * GEMM_STAGE_B);
        const uint32_t Ws_b = As_b + 18432;

#pragma unroll
        for (int ks = 0; ks < 4; ks++) {
            const uint32_t koff = (uint32_t)(ks * 32);
            uint32_t af[4][4];
#pragma unroll
            for (int mt = 0; mt < 4; mt++) {
                uint32_t aaddr = As_b + (uint32_t)((wm + mt * 16 + l16) * 144) + koff + ahalf;
                ldm_x4(af[mt][0], af[mt][1], af[mt][2], af[mt][3], aaddr);
            }
            uint32_t bf[4][2];
            {
                uint32_t baddr0 = Ws_b + (uint32_t)((wn + brow) * 144) + koff + bkoff;
                uint32_t baddr1 = Ws_b + (uint32_t)((wn + 16 + brow) * 144) + koff + bkoff;
                ldm_x4(bf[0][0], bf[0][1], bf[1][0], bf[1][1], baddr0);
                ldm_x4(bf[2][0], bf[2][1], bf[3][0], bf[3][1], baddr1);
            }
#pragma unroll
            for (int mt = 0; mt < 4; mt++)
#pragma unroll
                for (int nt = 0; nt < 4; nt++)
                    mma_f16(acc[mt][nt], af[mt], bf[nt][0], bf[nt][1]);
        }
        if (++sidx == 3) sidx = 0;
    }

    // ---- epilogue ----
    if (Chalf) {
        uint32_t* C32 = (uint32_t*)Chalf;
#pragma unroll
        for (int nt = 0; nt < 4; nt++) {
            int col = bn + wn + nt * 8 + 2 * q;
            float2 bb = *(const float2*)&bias[col];
            int colw = col >> 1;
#pragma unroll
            for (int mt = 0; mt < 4; mt++) {
                int row0 = bm + wm + mt * 16 + g;
                C32[(size_t)row0 * 512 + colw] =
                    fpack2(acc[mt][nt][0] + bb.x, acc[mt][nt][1] + bb.y);
                C32[(size_t)(row0 + 8) * 512 + colw] =
                    fpack2(acc[mt][nt][2] + bb.x, acc[mt][nt][3] + bb.y);
            }
        }
    } else {
#pragma unroll
        for (int nt = 0; nt < 4; nt++) {
            int col = bn + wn + nt * 8 + 2 * q;
            float2 bb = *(const float2*)&bias[col];
#pragma unroll
            for (int mt = 0; mt < 4; mt++) {
                int row0 = bm + wm + mt * 16 + g;
                *(float2*)&Cfloat[(size_t)row0 * HIDDEN + col] =
                    make_float2(acc[mt][nt][0] + bb.x, acc[mt][nt][1] + bb.y);
                *(float2*)&Cfloat[(size_t)(row0 + 8) * HIDDEN + col] =
                    make_float2(acc[mt][nt][2] + bb.x, acc[mt][nt][3] + bb.y);
            }
        }
    }
}

__global__ __launch_bounds__(256, 2)
void gemm_qkv_kernel(const float* __restrict__ bq, const float* __restrict__ bk,
                     const float* __restrict__ bv)
{
    extern __shared__ uint32_t gsm[];
    const int z = blockIdx.z;
    const __half* W = (z == 0) ? g_wq : (z == 1) ? g_wk : g_wv;
    const float* bias = (z == 0) ? bq : (z == 1) ? bk : bv;
    __half* C = (z == 0) ? g_q : (z == 1) ? g_k : g_v;
    gemm_body(g_x, W, bias, C, nullptr, gsm, blockIdx.y * 128, blockIdx.x * 128);
}

__global__ __launch_bounds__(256, 2)
void gemm_out_kernel(const float* __restrict__ bo, float* __restrict__ out)
{
    extern __shared__ uint32_t gsm[];
    gemm_body(g_ctx, g_wo, bo, nullptr, out, gsm, blockIdx.y * 128, blockIdx.x * 128);
}

// ============================================================================
// Flash attention v5: fp16 mma, cp.async double-buffered K/V, ldmatrix K/V,
// P register-resident, softmax base-2 with ex2.approx.f16x2 (P computed packed)
// and l-sum via mma against an all-ones B fragment (no FADDs, no l-shfls).
// ============================================================================
__global__ __launch_bounds__(128)
void attn_h_kernel()
{
    __shared__ uint32_t Kw[2][64 * 32];
    __shared__ uint32_t Vw[2][64 * 32];

    const int b = blockIdx.z;
    const int h = blockIdx.y;
    const int qb = blockIdx.x * 64;
    const int tid = threadIdx.x;
    const int wid = tid >> 5;
    const int lane = tid & 31;
    const int g = lane >> 2;
    const int q = lane & 3;

    const __half* kb_g = g_k + ((size_t)b * SEQ) * HIDDEN + h * HDIM;
    const __half* vb_g = g_v + ((size_t)b * SEQ) * HIDDEN + h * HDIM;
    const uint32_t smK[2] = { cvta_sh(Kw[0]), cvta_sh(Kw[1]) };
    const uint32_t smV[2] = { cvta_sh(Vw[0]), cvta_sh(Vw[1]) };

    auto stage = [&](int buf, int ktbase) {
#pragma unroll
        for (int i = 0; i < 4; i++) {
            int id = i * 128 + tid;
            int row = id >> 3;
            int c = id & 7;
            uint32_t doff = (uint32_t)(row * 128 + ((c ^ (row & 7)) << 4));
            cp16(smK[buf] + doff, kb_g + (size_t)(ktbase + row) * HIDDEN + c * 8);
            cp16(smV[buf] + doff, vb_g + (size_t)(ktbase + row) * HIDDEN + c * 8);
        }
    };

    stage(0, 0);
    cp_commit();

    // Q fragments scaled by 0.125 * log2(e) -> scores in log2 units
    const int qrow0 = qb + wid * 16 + g;
    const float QS = 0.18033688f;
    const uint32_t qs = fpack2(QS, QS);
    uint32_t qf[4][4];
    {
        const uint32_t* qp0 = (const uint32_t*)g_q +
                              ((size_t)b * SEQ + qrow0) * 512 + h * 32;
        const uint32_t* qp1 = qp0 + 8 * 512;
#pragma unroll
        for (int t = 0; t < 4; t++) {
            qf[t][0] = hmul2u(qp0[8 * t + q], qs);
            qf[t][1] = hmul2u(qp1[8 * t + q], qs);
            qf[t][2] = hmul2u(qp0[8 * t + q + 4], qs);
            qf[t][3] = hmul2u(qp1[8 * t + q + 4], qs);
        }
    }

    float oacc[8][4];
#pragma unroll
    for (int u = 0; u < 8; u++)
#pragma unroll
        for (int r = 0; r < 4; r++) oacc[u][r] = 0.0f;
    float m0 = -1e30f, m1 = -1e30f, l0 = 0.0f, l1 = 0.0f;

    const int lj = lane >> 3;
    const int ll = lane & 7;
    const uint32_t ONES2 = 0x3C003C00u;   // half2(1.0, 1.0)

    for (int it = 0; it < SEQ / 64; it++) {
        const int cur = it & 1;
        cp_wait0();
        __syncthreads();
        if (it + 1 < SEQ / 64) {
            stage(cur ^ 1, (it + 1) * 64);
            cp_commit();
        }

        // ---- S = Q K^T ----
        float sacc[8][4];
#pragma unroll
        for (int u = 0; u < 8; u++) {
#pragma unroll
            for (int r = 0; r < 4; r++) sacc[u][r] = 0.0f;
            uint32_t rowa = smK[cur] + (uint32_t)((8 * u + ll) * 128);
            uint32_t k0, k1, k2, k3, k4, k5, k6, k7;
            ldm_x4(k0, k1, k2, k3, rowa + (uint32_t)(((lj)     ^ ll) << 4));
            ldm_x4(k4, k5, k6, k7, rowa + (uint32_t)(((4 + lj) ^ ll) << 4));
            mma_f16(sacc[u], qf[0], k0, k1);
            mma_f16(sacc[u], qf[1], k2, k3);
            mma_f16(sacc[u], qf[2], k4, k5);
            mma_f16(sacc[u], qf[3], k6, k7);
        }

        // ---- online softmax (base-2, fp16 exp, l by mma) ----
        float mt0 = -1e30f, mt1 = -1e30f;
#pragma unroll
        for (int u = 0; u < 8; u++) {
            mt0 = fmaxf(mt0, fmaxf(sacc[u][0], sacc[u][1]));
            mt1 = fmaxf(mt1, fmaxf(sacc[u][2], sacc[u][3]));
        }
        mt0 = fmaxf(mt0, __shfl_xor_sync(0xffffffff, mt0, 1));
        mt0 = fmaxf(mt0, __shfl_xor_sync(0xffffffff, mt0, 2));
        mt1 = fmaxf(mt1, __shfl_xor_sync(0xffffffff, mt1, 1));
        mt1 = fmaxf(mt1, __shfl_xor_sync(0xffffffff, mt1, 2));

        float m0n = fmaxf(m0, mt0);
        float m1n = fmaxf(m1, mt1);
        float f0 = ex2f(m0 - m0n);
        float f1 = ex2f(m1 - m1n);
        m0 = m0n; m1 = m1n;

        uint32_t paf[4][4];
#pragma unroll
        for (int u = 0; u < 8; u++) {
            uint32_t d0 = fpack2(sacc[u][0] - m0n, sacc[u][1] - m0n);
            uint32_t d1 = fpack2(sacc[u][2] - m1n, sacc[u][3] - m1n);
            int base = (u & 1) << 1;
            paf[u >> 1][base]     = ex2h2(d0);   // rows g
            paf[u >> 1][base + 1] = ex2h2(d1);   // rows g+8
        }

        // l = P . 1  via 4 mmas against constant ones fragment
        float lacc[4] = {0.0f, 0.0f, 0.0f, 0.0f};
#pragma unroll
        for (int t = 0; t < 4; t++)
            mma_f16(lacc, paf[t], ONES2, ONES2);
        l0 = l0 * f0 + lacc[0];
        l1 = l1 * f1 + lacc[2];

#pragma unroll
        for (int u = 0; u < 8; u++) {
            oacc[u][0] *= f0; oacc[u][1] *= f0;
            oacc[u][2] *= f1; oacc[u][3] *= f1;
        }

        // ---- O += P V ----
        const int mat = lane >> 3;
        const int mrow = lane & 7;
#pragma unroll
        for (int t = 0; t < 4; t++) {
            uint32_t af[4] = { paf[t][0], paf[t][1], paf[t][2], paf[t][3] };
#pragma unroll
            for (int u2 = 0; u2 < 4; u2++) {
                int key = 16 * t + (mat & 1) * 8 + mrow;
                int cn  = 2 * u2 + (mat >> 1);
                uint32_t addr = smV[cur] + key * 128 + ((cn ^ (key & 7)) << 4);
                uint32_t b0, b1, b2, b3;
                ldm_x4_t(b0, b1, b2, b3, addr);
                mma_f16(oacc[2 * u2], af, b0, b1);
                mma_f16(oacc[2 * u2 + 1], af, b2, b3);
            }
        }
    }

    // ---- write ctx as fp16 ----
    float inv0 = 1.0f / l0;
    float inv1 = 1.0f / l1;
    uint32_t* op0 = (uint32_t*)g_ctx + ((size_t)b * SEQ + qrow0) * 512 + h * 32;
    uint32_t* op1 = op0 + 8 * 512;
#pragma unroll
    for (int u = 0; u < 8; u++) {
        op0[4 * u + q] = fpack2(oacc[u][0] * inv0, oacc[u][1] * inv0);
        op1[4 * u + q] = fpack2(oacc[u][2] * inv1, oacc[u][3] * inv1);
    }
}

// ============================================================================
// launcher — 4 graph nodes.
// ============================================================================
extern "C" void kernel_launch(void* const* d_in, const int* in_sizes, int n_in,
                              void* d_out, int out_size)
{
    (void)in_sizes; (void)n_in; (void)out_size;
    const float* x  = (const float*)d_in[0];
    const float* wq = (const float*)d_in[1];
    const float* bq = (const float*)d_in[2];
    const float* wk = (const float*)d_in[3];
    const float* bk = (const float*)d_in[4];
    const float* wv = (const float*)d_in[5];
    const float* bv = (const float*)d_in[6];
    const float* wo = (const float*)d_in[7];
    const float* bo = (const float*)d_in[8];
    float* out = (float*)d_out;

    static bool attr_set = false;
    if (!attr_set) {
        cudaFuncSetAttribute(gemm_qkv_kernel,
                             cudaFuncAttributeMaxDynamicSharedMemorySize, GEMM_SMEM3);
        cudaFuncSetAttribute(gemm_out_kernel,
                             cudaFuncAttributeMaxDynamicSharedMemorySize, GEMM_SMEM3);
        attr_set = true;
    }

    prep_kernel<<<NPREP / 256, 256>>>(x, wq, wk, wv, wo);

    dim3 qkvgrid(HIDDEN / 128, MROWS / 128, 3);
    gemm_qkv_kernel<<<qkvgrid, 256, GEMM_SMEM3>>>(bq, bk, bv);

    dim3 agrid(SEQ / 64, NHEADS, BATCH);
    attn_h_kernel<<<agrid, 128>>>();

    dim3 ogrid(HIDDEN / 128, MROWS / 128);
    gemm_out_kernel<<<ogrid, 256, GEMM_SMEM3>>>(bo, out);
}